// round 2
// baseline (speedup 1.0000x reference)
#include <cuda_runtime.h>
#include <math.h>

// ---------------- problem constants ----------------
#define BB   16
#define HH   56
#define WW   56
#define CC   384
#define C2   192
#define NHD  8
#define HD2  24
#define WIN  7
#define MM   (BB*HH*WW)        // 50176 tokens
#define HW   (HH*WW)           // 3136
#define KT   112               // key tile: 3136 = 28 * 112 exactly
#define SCALE_F 0.20412414523193154f   // 24^-0.5

// ---------------- scratch (device globals; no allocation allowed) ----------------
__device__ float g_xn  [(size_t)MM*CC];
__device__ float g_xen [(size_t)MM*C2];
__device__ float g_q   [(size_t)MM*CC];
__device__ float g_cut [(size_t)MM*C2];
__device__ float g_lx  [(size_t)MM*CC];
__device__ float g_clx [(size_t)MM*CC];
__device__ float g_a   [(size_t)MM*CC];
__device__ float g_kv  [(size_t)MM*CC];
__device__ float g_ef  [(size_t)MM*C2];
__device__ float g_efc [(size_t)MM*C2];
__device__ float g_xe2 [(size_t)MM*C2];
__device__ float g_m   [(size_t)BB*NHD*49*HD2];
__device__ float g_p   [(size_t)BB*NHD*49*HW];
__device__ float g_o   [(size_t)BB*NHD*49*HD2];
__device__ float g_attn[(size_t)MM*C2];
__device__ float g_cat [(size_t)MM*768];

// ---------------- LayerNorm (one block per row) ----------------
__global__ void ln_kernel(const float* __restrict__ x, const float* __restrict__ w,
                          const float* __restrict__ b, float* __restrict__ out, int C)
{
    int row = blockIdx.x;
    const float* xr = x + (size_t)row * C;
    float* orow = out + (size_t)row * C;

    float local[3];
    int n = 0; float s = 0.f;
    for (int i = threadIdx.x; i < C; i += 128) { float v = xr[i]; local[n++] = v; s += v; }

    __shared__ float sh[4];
    #pragma unroll
    for (int o = 16; o; o >>= 1) s += __shfl_xor_sync(0xffffffffu, s, o);
    if ((threadIdx.x & 31) == 0) sh[threadIdx.x >> 5] = s;
    __syncthreads();
    float mean = (sh[0] + sh[1] + sh[2] + sh[3]) / (float)C;
    __syncthreads();

    float ss = 0.f;
    for (int j = 0; j < n; j++) { float d = local[j] - mean; ss += d * d; }
    #pragma unroll
    for (int o = 16; o; o >>= 1) ss += __shfl_xor_sync(0xffffffffu, ss, o);
    if ((threadIdx.x & 31) == 0) sh[threadIdx.x >> 5] = ss;
    __syncthreads();
    float var  = (sh[0] + sh[1] + sh[2] + sh[3]) / (float)C;
    float rstd = rsqrtf(var + 1e-6f);

    n = 0;
    for (int i = threadIdx.x; i < C; i += 128)
        orow[i] = (local[n++] - mean) * rstd * w[i] + b[i];
}

// ---------------- generic SGEMM: C = A[M,K] @ B[K,N] + bias, optional exact gelu ----------------
#define BM 128
#define BN 128
#define BKK 8
__global__ __launch_bounds__(256)
void sgemm_kernel(const float* __restrict__ A, const float* __restrict__ B,
                  const float* __restrict__ bias, float* __restrict__ C,
                  int M, int N, int K, int act)
{
    __shared__ float As[BKK][BM];
    __shared__ float Bs[BKK][BN];
    int tid = threadIdx.x;
    int bm = blockIdx.y, bn = blockIdx.x;

    int rowA = tid >> 1;            // 0..127
    int colA = (tid & 1) * 4;       // 0 or 4
    int rowB = tid >> 5;            // 0..7
    int colB = (tid & 31) * 4;      // 0..124
    int bcol0 = bn * BN;

    const float* Ab = A + (size_t)(bm * BM) * K;
    float acc[8][8] = {};
    int tRow = (tid >> 4) * 8;
    int tCol = (tid & 15) * 8;

    for (int kk = 0; kk < K; kk += BKK) {
        float4 av = *(const float4*)(Ab + (size_t)rowA * K + kk + colA);
        As[colA + 0][rowA] = av.x; As[colA + 1][rowA] = av.y;
        As[colA + 2][rowA] = av.z; As[colA + 3][rowA] = av.w;

        float4 bv = make_float4(0.f, 0.f, 0.f, 0.f);
        if (bcol0 + colB < N)
            bv = *(const float4*)(B + (size_t)(kk + rowB) * N + bcol0 + colB);
        *(float4*)&Bs[rowB][colB] = bv;
        __syncthreads();

        #pragma unroll
        for (int k = 0; k < BKK; k++) {
            float ra[8], rb[8];
            #pragma unroll
            for (int i = 0; i < 8; i++) ra[i] = As[k][tRow + i];
            #pragma unroll
            for (int j = 0; j < 8; j++) rb[j] = Bs[k][tCol + j];
            #pragma unroll
            for (int i = 0; i < 8; i++)
                #pragma unroll
                for (int j = 0; j < 8; j++) acc[i][j] += ra[i] * rb[j];
        }
        __syncthreads();
    }

    #pragma unroll
    for (int i = 0; i < 8; i++) {
        size_t row = (size_t)bm * BM + tRow + i;
        #pragma unroll
        for (int j = 0; j < 8; j++) {
            int col = bcol0 + tCol + j;
            if (col < N) {
                float v = acc[i][j] + bias[col];
                if (act == 1) v = 0.5f * v * (1.0f + erff(v * 0.70710678118654752f));
                C[row * (size_t)N + col] = v;
            }
        }
    }
}

// ---------------- pooled shortcut queries + scl GEMM + SCALE fold ----------------
__global__ void pool_scl_kernel(const float* __restrict__ xn, const float* __restrict__ xen,
                                const float* __restrict__ sw, const float* __restrict__ sb,
                                float* __restrict__ mout)
{
    __shared__ float pooled[576];
    int blk = blockIdx.x; int b = blk / 49, qi = blk % 49;
    int py = qi / 7, px = qi % 7;
    int tid = threadIdx.x;    // 192 threads

    for (int ch = tid; ch < 576; ch += 192) {
        float s = 0.f;
        if (ch < CC) {
            const float* base = xn + ((size_t)(b * HH + py * 8) * WW + px * 8) * CC + ch;
            #pragma unroll
            for (int hy = 0; hy < 8; hy++)
                #pragma unroll
                for (int wx = 0; wx < 8; wx++) s += base[(size_t)(hy * WW + wx) * CC];
        } else {
            const float* base = xen + ((size_t)(b * HH + py * 8) * WW + px * 8) * C2 + (ch - CC);
            #pragma unroll
            for (int hy = 0; hy < 8; hy++)
                #pragma unroll
                for (int wx = 0; wx < 8; wx++) s += base[(size_t)(hy * WW + wx) * C2];
        }
        pooled[ch] = s * (1.0f / 64.0f);
    }
    __syncthreads();

    int j = tid;                 // output channel 0..191
    float a = sb[j];
    for (int kk = 0; kk < 576; kk++) a += pooled[kk] * sw[(size_t)kk * C2 + j];
    a *= SCALE_F;
    mout[((size_t)(b * NHD + j / HD2) * 49 + qi) * HD2 + (j % HD2)] = a;
}

// ---------------- depthwise 7x7 conv (channels-last), 14x14 tile x 8-ch chunk ----------------
__global__ void dwconv7_kernel(const float* __restrict__ in, const float* __restrict__ w,
                               const float* __restrict__ bias, float* __restrict__ out, int C)
{
    __shared__ float s_in[8][400];   // 20x20 halo tile
    __shared__ float s_w[8][49];
    __shared__ float s_b[8];
    __shared__ float s_out[196][8];

    int nchunk = C >> 3;
    int b  = blockIdx.z / nchunk;
    int c0 = (blockIdx.z % nchunk) << 3;
    int ty0 = blockIdx.y * 14, tx0 = blockIdx.x * 14;
    int tid = threadIdx.x;   // 196 threads

    for (int idx = tid; idx < 3200; idx += 196) {
        int p = idx >> 3, cc = idx & 7;
        int iy = p / 20, ix = p % 20;
        int gy = ty0 + iy - 3, gx = tx0 + ix - 3;
        float v = 0.f;
        if (gy >= 0 && gy < HH && gx >= 0 && gx < WW)
            v = in[(((size_t)b * HH + gy) * WW + gx) * C + c0 + cc];
        s_in[cc][p] = v;
    }
    for (int idx = tid; idx < 392; idx += 196)
        s_w[idx / 49][idx % 49] = w[(size_t)(c0 + idx / 49) * 49 + idx % 49];
    if (tid < 8) s_b[tid] = bias[c0 + tid];
    __syncthreads();

    int ty = tid / 14, tx = tid % 14;
    float acc[8];
    #pragma unroll
    for (int cc = 0; cc < 8; cc++) acc[cc] = s_b[cc];
    #pragma unroll
    for (int ky = 0; ky < 7; ky++)
        #pragma unroll
        for (int kx = 0; kx < 7; kx++) {
            int p = (ty + ky) * 20 + tx + kx;
            #pragma unroll
            for (int cc = 0; cc < 8; cc++) acc[cc] += s_in[cc][p] * s_w[cc][ky * 7 + kx];
        }
    #pragma unroll
    for (int cc = 0; cc < 8; cc++) s_out[tid][cc] = acc[cc];
    __syncthreads();

    for (int idx = tid; idx < 1568; idx += 196) {
        int p = idx >> 3, cc = idx & 7;
        int oy = ty0 + p / 14, ox = tx0 + p % 14;
        out[(((size_t)b * HH + oy) * WW + ox) * C + c0 + cc] = s_out[p][cc];
    }
}

// ---------------- attention: one block per (b,h); p scratch in global ----------------
// key tile = 112 (divides HW=3136 exactly: 28 tiles). The previous 128 tile
// overran the b,h slice and corrupted neighboring q rows (round-1 bug).
__global__ __launch_bounds__(256)
void attn_kernel(const float* __restrict__ kvb, const float* __restrict__ m,
                 float* __restrict__ p, float* __restrict__ o)
{
    __shared__ float s_m[49 * 24];
    __shared__ float s_kv[KT * 24];
    __shared__ float s_pt[49 * KT];
    __shared__ float s_max[49], s_sum[49];

    int bh = blockIdx.x; int b = bh >> 3; int h = bh & 7;
    int tid = threadIdx.x, lane = tid & 31, wid = tid >> 5;

    const float* mrow = m + (size_t)bh * 49 * 24;
    for (int i = tid; i < 1176; i += 256) s_m[i] = mrow[i];
    float* prow = p + (size_t)bh * 49 * HW;
    const float* kbase = kvb + (size_t)b * HW * CC + h * HD2;
    const float* vbase = kbase + C2;

    float lmax[7];
    #pragma unroll
    for (int j = 0; j < 7; j++) lmax[j] = -1e30f;
    __syncthreads();

    // phase 1: scores -> global, per-warp running max
    for (int kt = 0; kt < HW; kt += KT) {
        for (int i = tid; i < KT * 24; i += 256) {
            s_kv[i] = kbase[(size_t)(kt + i / 24) * CC + i % 24];
        }
        __syncthreads();
        for (int j = 0;; j++) {
            int q = wid + 8 * j; if (q >= 49) break;
            const float* mq = s_m + q * 24;
            for (int kk = lane; kk < KT; kk += 32) {
                const float* kr = s_kv + kk * 24;
                float s = 0.f;
                #pragma unroll
                for (int d = 0; d < 24; d++) s += mq[d] * kr[d];
                prow[(size_t)q * HW + kt + kk] = s;
                lmax[j] = fmaxf(lmax[j], s);
            }
        }
        __syncthreads();
    }
    for (int j = 0;; j++) {
        int q = wid + 8 * j; if (q >= 49) break;
        float v = lmax[j];
        #pragma unroll
        for (int off = 16; off; off >>= 1) v = fmaxf(v, __shfl_xor_sync(0xffffffffu, v, off));
        if (lane == 0) s_max[q] = v;
    }
    __syncthreads();

    // phase 2: exp + row sum (p overwritten with unnormalized exp)
    for (int j = 0;; j++) {
        int q = wid + 8 * j; if (q >= 49) break;
        float mx = s_max[q]; float sum = 0.f;
        float* pr = prow + (size_t)q * HW;
        for (int kk = lane; kk < HW; kk += 32) {
            float e = expf(pr[kk] - mx);
            pr[kk] = e; sum += e;
        }
        #pragma unroll
        for (int off = 16; off; off >>= 1) sum += __shfl_xor_sync(0xffffffffu, sum, off);
        if (lane == 0) s_sum[q] = sum;
    }
    __syncthreads();

    // phase 3: o = (p @ v) / sum, 5 register accumulators per thread
    float acc[5] = {0.f, 0.f, 0.f, 0.f, 0.f};
    for (int kt = 0; kt < HW; kt += KT) {
        for (int i = tid; i < KT * 24; i += 256) {
            s_kv[i] = vbase[(size_t)(kt + i / 24) * CC + i % 24];
        }
        for (int i = tid; i < 49 * KT; i += 256) {
            int q = i / KT, kk = i % KT;
            s_pt[i] = prow[(size_t)q * HW + kt + kk];
        }
        __syncthreads();
        #pragma unroll
        for (int r = 0; r < 5; r++) {
            int idx = tid + 256 * r;
            if (idx < 1176) {
                int q = idx / 24, d = idx % 24;
                float a = acc[r];
                const float* pq = s_pt + q * KT;
                #pragma unroll 8
                for (int kk = 0; kk < KT; kk++) a += pq[kk] * s_kv[kk * 24 + d];
                acc[r] = a;
            }
        }
        __syncthreads();
    }
    float* orow = o + (size_t)bh * 49 * 24;
    #pragma unroll
    for (int r = 0; r < 5; r++) {
        int idx = tid + 256 * r;
        if (idx < 1176) orow[idx] = acc[r] / s_sum[idx / 24];
    }
}

// ---------------- bilinear 7->56 upsample (jax half-pixel + boundary renorm == clamped lerp) ----------------
__global__ void upsample_kernel(const float* __restrict__ o, float* __restrict__ attn)
{
    int x = blockIdx.x, y = blockIdx.y, b = blockIdx.z;
    int c = threadIdx.x;   // 192
    float fy = (y + 0.5f) * 0.125f - 0.5f;
    float fx = (x + 0.5f) * 0.125f - 0.5f;
    int y0 = (int)floorf(fy); float ty = fy - (float)y0;
    int x0 = (int)floorf(fx); float tx = fx - (float)x0;
    int y0c = max(y0, 0), y1c = min(y0 + 1, 6);
    int x0c = max(x0, 0), x1c = min(x0 + 1, 6);

    int h = c / HD2, d = c % HD2;
    const float* ob = o + ((size_t)(b * NHD + h) * 49) * HD2 + d;
    float v00 = ob[(y0c * 7 + x0c) * HD2], v01 = ob[(y0c * 7 + x1c) * HD2];
    float v10 = ob[(y1c * 7 + x0c) * HD2], v11 = ob[(y1c * 7 + x1c) * HD2];
    float v = (1.f - ty) * ((1.f - tx) * v00 + tx * v01) + ty * ((1.f - tx) * v10 + tx * v11);
    attn[(((size_t)b * HH + y) * WW + x) * C2 + c] = v;
}

// ---------------- elementwise concat: [q*a | attn | cut*xe2] ----------------
__global__ void cat_kernel(const float* __restrict__ q, const float* __restrict__ a,
                           const float* __restrict__ attn, const float* __restrict__ cut,
                           const float* __restrict__ xe2, float* __restrict__ cat)
{
    size_t idx = (size_t)blockIdx.x * blockDim.x + threadIdx.x;
    if (idx >= (size_t)MM * 768) return;
    size_t row = idx / 768; int col = (int)(idx % 768);
    float v;
    if (col < 384)      v = q[row * 384 + col] * a[row * 384 + col];
    else if (col < 576) v = attn[row * 192 + col - 384];
    else { size_t off = row * 192 + col - 576; v = cut[off] * xe2[off]; }
    cat[idx] = v;
}

// ---------------- launch ----------------
extern "C" void kernel_launch(void* const* d_in, const int* in_sizes, int n_in,
                              void* d_out, int out_size)
{
    const float* x       = (const float*)d_in[0];
    const float* x_e     = (const float*)d_in[1];
    const float* norm_w  = (const float*)d_in[2];
    const float* norm_b  = (const float*)d_in[3];
    const float* norme_w = (const float*)d_in[4];
    const float* norme_b = (const float*)d_in[5];
    const float* q_w     = (const float*)d_in[6];
    const float* q_b     = (const float*)d_in[7];
    const float* qcut_w  = (const float*)d_in[8];
    const float* qcut_b  = (const float*)d_in[9];
    const float* a_w     = (const float*)d_in[10];
    const float* a_b     = (const float*)d_in[11];
    const float* l_w     = (const float*)d_in[12];
    const float* l_b     = (const float*)d_in[13];
    const float* conv_w  = (const float*)d_in[14];
    const float* conv_b  = (const float*)d_in[15];
    const float* econv_w = (const float*)d_in[16];
    const float* econv_b = (const float*)d_in[17];
    const float* efore_w = (const float*)d_in[18];
    const float* efore_b = (const float*)d_in[19];
    const float* eback_w = (const float*)d_in[20];
    const float* eback_b = (const float*)d_in[21];
    const float* kv_w    = (const float*)d_in[22];
    const float* kv_b    = (const float*)d_in[23];
    const float* scl_w   = (const float*)d_in[24];
    const float* scl_b   = (const float*)d_in[25];
    const float* proj_w  = (const float*)d_in[26];
    const float* proj_b  = (const float*)d_in[27];
    const float* proje_w = (const float*)d_in[28];
    const float* proje_b = (const float*)d_in[29];
    float* out = (float*)d_out;
    float* out_x  = out;                        // [M,384]
    float* out_xe = out + (size_t)MM * CC;      // [M,192]

    float *xn, *xen, *qb, *cutb, *lx, *clx, *ab, *kvb, *ef, *efc, *xe2, *mb, *pb, *ob, *attnb, *catb;
    cudaGetSymbolAddress((void**)&xn,   g_xn);
    cudaGetSymbolAddress((void**)&xen,  g_xen);
    cudaGetSymbolAddress((void**)&qb,   g_q);
    cudaGetSymbolAddress((void**)&cutb, g_cut);
    cudaGetSymbolAddress((void**)&lx,   g_lx);
    cudaGetSymbolAddress((void**)&clx,  g_clx);
    cudaGetSymbolAddress((void**)&ab,   g_a);
    cudaGetSymbolAddress((void**)&kvb,  g_kv);
    cudaGetSymbolAddress((void**)&ef,   g_ef);
    cudaGetSymbolAddress((void**)&efc,  g_efc);
    cudaGetSymbolAddress((void**)&xe2,  g_xe2);
    cudaGetSymbolAddress((void**)&mb,   g_m);
    cudaGetSymbolAddress((void**)&pb,   g_p);
    cudaGetSymbolAddress((void**)&ob,   g_o);
    cudaGetSymbolAddress((void**)&attnb,g_attn);
    cudaGetSymbolAddress((void**)&catb, g_cat);

    // 1) LayerNorms
    ln_kernel<<<MM, 128>>>(x,   norm_w,  norm_b,  xn,  CC);
    ln_kernel<<<MM, 128>>>(x_e, norme_w, norme_b, xen, C2);

    // 2) pooled shortcut queries -> m (scaled)
    pool_scl_kernel<<<BB * 49, 192>>>(xn, xen, scl_w, scl_b, mb);

    // 3) q / cut / lx(gelu) GEMMs
    dim3 gN384(3, MM / BM), gN192(2, MM / BM);
    sgemm_kernel<<<gN384, 256>>>(xn, q_w,    q_b,    qb,   MM, 384, 384, 0);
    sgemm_kernel<<<gN192, 256>>>(xn, qcut_w, qcut_b, cutb, MM, 192, 384, 0);
    sgemm_kernel<<<gN384, 256>>>(xn, l_w,    l_b,    lx,   MM, 384, 384, 1);

    // 4) depthwise conv on lx, then a / kv GEMMs
    dwconv7_kernel<<<dim3(4, 4, BB * (CC / 8)), 196>>>(lx, conv_w, conv_b, clx, CC);
    sgemm_kernel<<<gN384, 256>>>(clx, a_w,  a_b,  ab,  MM, 384, 384, 0);
    sgemm_kernel<<<gN384, 256>>>(lx,  kv_w, kv_b, kvb, MM, 384, 384, 0);

    // 5) attention + bilinear upsample
    attn_kernel<<<BB * NHD, 256>>>(kvb, mb, pb, ob);
    upsample_kernel<<<dim3(WW, HH, BB), C2>>>(ob, attnb);

    // 6) x_e depthwise branch
    sgemm_kernel<<<gN192, 256>>>(xen, efore_w, efore_b, ef, MM, 192, 192, 0);
    dwconv7_kernel<<<dim3(4, 4, BB * (C2 / 8)), 196>>>(ef, econv_w, econv_b, efc, C2);
    sgemm_kernel<<<gN192, 256>>>(efc, eback_w, eback_b, xe2, MM, 192, 192, 0);

    // 7) concat + final projections
    size_t tot = (size_t)MM * 768;
    cat_kernel<<<(unsigned)((tot + 255) / 256), 256>>>(qb, ab, attnb, cutb, xe2, catb);
    sgemm_kernel<<<gN384, 256>>>(catb, proj_w,  proj_b,  out_x,  MM, 384, 768, 0);
    sgemm_kernel<<<gN192, 256>>>(catb, proje_w, proje_b, out_xe, MM, 192, 768, 0);
}

// round 4
// speedup vs baseline: 3.3530x; 3.3530x over previous
#include <cuda_runtime.h>
#include <math.h>
#include <stdint.h>

// ---------------- problem constants ----------------
#define BB   16
#define HH   56
#define WW   56
#define CC   384
#define C2   192
#define NHD  8
#define HD2  24
#define MM   (BB*HH*WW)        // 50176 tokens
#define HW   (HH*WW)           // 3136
#define KT   112               // attn key tile: 3136 = 28*112
#define SCALE_F 0.20412414523193154f

// ---------------- scratch (device globals; no allocation allowed) ----------------
__device__ float g_xn  [(size_t)MM*CC];
__device__ float g_xen [(size_t)MM*C2];
__device__ float g_q   [(size_t)MM*CC];
__device__ float g_cut [(size_t)MM*C2];
__device__ float g_lx  [(size_t)MM*CC];
__device__ float g_clx [(size_t)MM*CC];
__device__ float g_a   [(size_t)MM*CC];
__device__ float g_kv  [(size_t)MM*CC];
__device__ float g_ef  [(size_t)MM*C2];
__device__ float g_efc [(size_t)MM*C2];
__device__ float g_xe2 [(size_t)MM*C2];
__device__ float g_m   [(size_t)BB*NHD*49*HD2];
__device__ float g_p   [(size_t)BB*NHD*49*HW];
__device__ float g_o   [(size_t)BB*NHD*49*HD2];
__device__ float g_attn[(size_t)MM*C2];
__device__ float g_cat [(size_t)MM*768];

// transposed (+zero-padded to 128-multiple rows) weights: Bt[n*K + k] = W[k*N + n]
__device__ float g_tq    [384*384];
__device__ float g_tl    [384*384];
__device__ float g_ta    [384*384];
__device__ float g_tkv   [384*384];
__device__ float g_tqcut [256*384];
__device__ float g_tefore[256*192];
__device__ float g_teback[256*192];
__device__ float g_tproj [384*768];
__device__ float g_tproje[256*768];

// ---------------- PTX helpers (non-'a' features only: sm_80+ path) ----------------
__device__ __forceinline__ uint32_t smem_u32(const void* p) {
    uint32_t r;
    asm("{ .reg .u64 t; cvta.to.shared.u64 t, %1; cvt.u32.u64 %0, t; }" : "=r"(r) : "l"(p));
    return r;
}
__device__ __forceinline__ void cp_async16(uint32_t dst, const void* src) {
    asm volatile("cp.async.ca.shared.global [%0], [%1], 16;" :: "r"(dst), "l"(src) : "memory");
}
__device__ __forceinline__ void cp_commit() {
    asm volatile("cp.async.commit_group;" ::: "memory");
}
template<int N>
__device__ __forceinline__ void cp_wait() {
    asm volatile("cp.async.wait_group %0;" :: "n"(N) : "memory");
}
__device__ __forceinline__ uint32_t f2tf32(float f) {
    uint32_t r;
    asm("cvt.rna.tf32.f32 %0, %1;" : "=r"(r) : "f"(f));
    return r;
}
__device__ __forceinline__ void mma_tf32(float* c, const uint32_t* a, uint32_t b0, uint32_t b1) {
    asm volatile(
        "mma.sync.aligned.m16n8k8.row.col.f32.tf32.tf32.f32 "
        "{%0,%1,%2,%3}, {%4,%5,%6,%7}, {%8,%9}, {%0,%1,%2,%3};"
        : "+f"(c[0]), "+f"(c[1]), "+f"(c[2]), "+f"(c[3])
        : "r"(a[0]), "r"(a[1]), "r"(a[2]), "r"(a[3]), "r"(b0), "r"(b1));
}

// ---------------- weight transpose + pad ----------------
__global__ void transpose_pad_kernel(const float* __restrict__ Bin, float* __restrict__ Bt,
                                     int K, int N, int Npad)
{
    int idx = blockIdx.x * 256 + threadIdx.x;
    if (idx >= Npad * K) return;
    int n = idx / K, k = idx % K;
    Bt[idx] = (n < N) ? Bin[(size_t)k * N + n] : 0.f;
}

// ---------------- tf32 tensor-core GEMM: C[M,N] = A[M,K] @ Bt[N,K]^T + bias ----------------
// 128x128 CTA tile, BK=32, cp.async double buffer, 8 warps x (32x64) warp tiles.
// smem stride 36 floats: fragment LDS bank = (4*(lane/4)+lane%4)%32 -> conflict-free.
#define SSTRIDE 36
#define STAGE_F (128 * SSTRIDE * 2)          // floats per stage (As + Bs)
#define GEMM_SMEM (2 * STAGE_F * 4)          // 73728 bytes
__global__ __launch_bounds__(256, 2)
void tf32_gemm_kernel(const float* __restrict__ A, const float* __restrict__ Bt,
                      const float* __restrict__ bias, float* __restrict__ C,
                      int N, int K, int act)
{
    extern __shared__ float smf[];
    const int tid  = threadIdx.x;
    const int lane = tid & 31, wid = tid >> 5;
    const int bn = blockIdx.x, bm = blockIdx.y;
    const int warpM = (wid & 3) * 32;
    const int warpN = (wid >> 2) * 64;

    const float* Ab = A  + (size_t)bm * 128 * K;
    const float* Bb = Bt + (size_t)bn * 128 * K;

    uint32_t sb = smem_u32(smf);
    const int ldrow = tid >> 3;              // 0..31 (+32 per it)
    const int ldcol = (tid & 7) * 4;

    float acc[2][8][4];
    #pragma unroll
    for (int i = 0; i < 2; i++)
        #pragma unroll
        for (int j = 0; j < 8; j++)
            #pragma unroll
            for (int t = 0; t < 4; t++) acc[i][j][t] = 0.f;

    const int NC = K >> 5;

    // prefetch chunk 0 into stage 0
    {
        const float* ga = Ab;
        const float* gb = Bb;
        #pragma unroll
        for (int it = 0; it < 4; it++) {
            int row = ldrow + it * 32;
            uint32_t off = (uint32_t)(row * SSTRIDE + ldcol) * 4;
            cp_async16(sb + off, ga + (size_t)row * K + ldcol);
            cp_async16(sb + 128 * SSTRIDE * 4 + off, gb + (size_t)row * K + ldcol);
        }
        cp_commit();
    }

    for (int c = 0; c < NC; c++) {
        int buf = c & 1;
        if (c + 1 < NC) {
            int nbuf = (c + 1) & 1;
            const float* ga = Ab + (c + 1) * 32;
            const float* gb = Bb + (c + 1) * 32;
            uint32_t stage = sb + (uint32_t)nbuf * STAGE_F * 4;
            #pragma unroll
            for (int it = 0; it < 4; it++) {
                int row = ldrow + it * 32;
                uint32_t off = (uint32_t)(row * SSTRIDE + ldcol) * 4;
                cp_async16(stage + off, ga + (size_t)row * K + ldcol);
                cp_async16(stage + 128 * SSTRIDE * 4 + off, gb + (size_t)row * K + ldcol);
            }
            cp_commit();
            cp_wait<1>();
        } else {
            cp_wait<0>();
        }
        __syncthreads();

        const float* As = smf + buf * STAGE_F;
        const float* Bs = As + 128 * SSTRIDE;

        #pragma unroll
        for (int ks = 0; ks < 4; ks++) {
            int k0 = ks * 8 + (lane & 3);
            int rr = lane >> 2;
            uint32_t afr[2][4];
            #pragma unroll
            for (int mt = 0; mt < 2; mt++) {
                int m0 = warpM + mt * 16 + rr;
                afr[mt][0] = f2tf32(As[m0 * SSTRIDE + k0]);
                afr[mt][1] = f2tf32(As[(m0 + 8) * SSTRIDE + k0]);
                afr[mt][2] = f2tf32(As[m0 * SSTRIDE + k0 + 4]);
                afr[mt][3] = f2tf32(As[(m0 + 8) * SSTRIDE + k0 + 4]);
            }
            #pragma unroll
            for (int nt = 0; nt < 8; nt++) {
                int n0 = warpN + nt * 8 + rr;
                uint32_t b0 = f2tf32(Bs[n0 * SSTRIDE + k0]);
                uint32_t b1 = f2tf32(Bs[n0 * SSTRIDE + k0 + 4]);
                mma_tf32(acc[0][nt], afr[0], b0, b1);
                mma_tf32(acc[1][nt], afr[1], b0, b1);
            }
        }
        __syncthreads();
    }

    // epilogue: bias + optional exact gelu, float2 stores
    #pragma unroll
    for (int mt = 0; mt < 2; mt++) {
        size_t row0 = (size_t)bm * 128 + warpM + mt * 16 + (lane >> 2);
        #pragma unroll
        for (int nt = 0; nt < 8; nt++) {
            int gcol = bn * 128 + warpN + nt * 8 + (lane & 3) * 2;
            if (gcol < N) {
                float bs0 = bias[gcol], bs1 = bias[gcol + 1];
                float v0 = acc[mt][nt][0] + bs0;
                float v1 = acc[mt][nt][1] + bs1;
                float v2 = acc[mt][nt][2] + bs0;
                float v3 = acc[mt][nt][3] + bs1;
                if (act) {
                    v0 = 0.5f*v0*(1.f+erff(v0*0.70710678118654752f));
                    v1 = 0.5f*v1*(1.f+erff(v1*0.70710678118654752f));
                    v2 = 0.5f*v2*(1.f+erff(v2*0.70710678118654752f));
                    v3 = 0.5f*v3*(1.f+erff(v3*0.70710678118654752f));
                }
                float2 p0; p0.x = v0; p0.y = v1;
                float2 p1; p1.x = v2; p1.y = v3;
                *(float2*)(C + row0 * (size_t)N + gcol) = p0;
                *(float2*)(C + (row0 + 8) * (size_t)N + gcol) = p1;
            }
        }
    }
}

// ---------------- LayerNorm (one block per row) ----------------
__global__ void ln_kernel(const float* __restrict__ x, const float* __restrict__ w,
                          const float* __restrict__ b, float* __restrict__ out, int C)
{
    int row = blockIdx.x;
    const float* xr = x + (size_t)row * C;
    float* orow = out + (size_t)row * C;

    float local[3];
    int n = 0; float s = 0.f;
    for (int i = threadIdx.x; i < C; i += 128) { float v = xr[i]; local[n++] = v; s += v; }

    __shared__ float sh[4];
    #pragma unroll
    for (int o = 16; o; o >>= 1) s += __shfl_xor_sync(0xffffffffu, s, o);
    if ((threadIdx.x & 31) == 0) sh[threadIdx.x >> 5] = s;
    __syncthreads();
    float mean = (sh[0] + sh[1] + sh[2] + sh[3]) / (float)C;
    __syncthreads();

    float ss = 0.f;
    for (int j = 0; j < n; j++) { float d = local[j] - mean; ss += d * d; }
    #pragma unroll
    for (int o = 16; o; o >>= 1) ss += __shfl_xor_sync(0xffffffffu, ss, o);
    if ((threadIdx.x & 31) == 0) sh[threadIdx.x >> 5] = ss;
    __syncthreads();
    float var  = (sh[0] + sh[1] + sh[2] + sh[3]) / (float)C;
    float rstd = rsqrtf(var + 1e-6f);

    n = 0;
    for (int i = threadIdx.x; i < C; i += 128)
        orow[i] = (local[n++] - mean) * rstd * w[i] + b[i];
}

// ---------------- pooled shortcut queries + scl GEMM + SCALE fold ----------------
__global__ void pool_scl_kernel(const float* __restrict__ xn, const float* __restrict__ xen,
                                const float* __restrict__ sw, const float* __restrict__ sb,
                                float* __restrict__ mout)
{
    __shared__ float pooled[576];
    int blk = blockIdx.x; int b = blk / 49, qi = blk % 49;
    int py = qi / 7, px = qi % 7;
    int tid = threadIdx.x;    // 192 threads

    for (int ch = tid; ch < 576; ch += 192) {
        float s = 0.f;
        if (ch < CC) {
            const float* base = xn + ((size_t)(b * HH + py * 8) * WW + px * 8) * CC + ch;
            #pragma unroll
            for (int hy = 0; hy < 8; hy++)
                #pragma unroll
                for (int wx = 0; wx < 8; wx++) s += base[(size_t)(hy * WW + wx) * CC];
        } else {
            const float* base = xen + ((size_t)(b * HH + py * 8) * WW + px * 8) * C2 + (ch - CC);
            #pragma unroll
            for (int hy = 0; hy < 8; hy++)
                #pragma unroll
                for (int wx = 0; wx < 8; wx++) s += base[(size_t)(hy * WW + wx) * C2];
        }
        pooled[ch] = s * (1.0f / 64.0f);
    }
    __syncthreads();

    int j = tid;
    float a = sb[j];
    for (int kk = 0; kk < 576; kk++) a += pooled[kk] * sw[(size_t)kk * C2 + j];
    a *= SCALE_F;
    mout[((size_t)(b * NHD + j / HD2) * 49 + qi) * HD2 + (j % HD2)] = a;
}

// ---------------- depthwise 7x7 conv (channels-last), 14x14 tile x 8-ch chunk ----------------
__global__ void dwconv7_kernel(const float* __restrict__ in, const float* __restrict__ w,
                               const float* __restrict__ bias, float* __restrict__ out, int C)
{
    __shared__ float s_in[8][400];
    __shared__ float s_w[8][49];
    __shared__ float s_b[8];
    __shared__ float s_out[196][8];

    int nchunk = C >> 3;
    int b  = blockIdx.z / nchunk;
    int c0 = (blockIdx.z % nchunk) << 3;
    int ty0 = blockIdx.y * 14, tx0 = blockIdx.x * 14;
    int tid = threadIdx.x;   // 196

    for (int idx = tid; idx < 3200; idx += 196) {
        int p = idx >> 3, cc = idx & 7;
        int iy = p / 20, ix = p % 20;
        int gy = ty0 + iy - 3, gx = tx0 + ix - 3;
        float v = 0.f;
        if (gy >= 0 && gy < HH && gx >= 0 && gx < WW)
            v = in[(((size_t)b * HH + gy) * WW + gx) * C + c0 + cc];
        s_in[cc][p] = v;
    }
    for (int idx = tid; idx < 392; idx += 196)
        s_w[idx / 49][idx % 49] = w[(size_t)(c0 + idx / 49) * 49 + idx % 49];
    if (tid < 8) s_b[tid] = bias[c0 + tid];
    __syncthreads();

    int ty = tid / 14, tx = tid % 14;
    float acc[8];
    #pragma unroll
    for (int cc = 0; cc < 8; cc++) acc[cc] = s_b[cc];
    #pragma unroll
    for (int ky = 0; ky < 7; ky++)
        #pragma unroll
        for (int kx = 0; kx < 7; kx++) {
            int p = (ty + ky) * 20 + tx + kx;
            #pragma unroll
            for (int cc = 0; cc < 8; cc++) acc[cc] += s_in[cc][p] * s_w[cc][ky * 7 + kx];
        }
    #pragma unroll
    for (int cc = 0; cc < 8; cc++) s_out[tid][cc] = acc[cc];
    __syncthreads();

    for (int idx = tid; idx < 1568; idx += 196) {
        int p = idx >> 3, cc = idx & 7;
        int oy = ty0 + p / 14, ox = tx0 + p % 14;
        out[(((size_t)b * HH + oy) * WW + ox) * C + c0 + cc] = s_out[p][cc];
    }
}

// ---------------- attention (KT=112 divides HW exactly) ----------------
__global__ __launch_bounds__(256)
void attn_kernel(const float* __restrict__ kvb, const float* __restrict__ m,
                 float* __restrict__ p, float* __restrict__ o)
{
    __shared__ float s_m[49 * 24];
    __shared__ float s_kv[KT * 24];
    __shared__ float s_pt[49 * KT];
    __shared__ float s_max[49], s_sum[49];

    int bh = blockIdx.x; int b = bh >> 3; int h = bh & 7;
    int tid = threadIdx.x, lane = tid & 31, wid = tid >> 5;

    const float* mrow = m + (size_t)bh * 49 * 24;
    for (int i = tid; i < 1176; i += 256) s_m[i] = mrow[i];
    float* prow = p + (size_t)bh * 49 * HW;
    const float* kbase = kvb + (size_t)b * HW * CC + h * HD2;
    const float* vbase = kbase + C2;

    float lmax[7];
    #pragma unroll
    for (int j = 0; j < 7; j++) lmax[j] = -1e30f;
    __syncthreads();

    for (int kt = 0; kt < HW; kt += KT) {
        for (int i = tid; i < KT * 24; i += 256)
            s_kv[i] = kbase[(size_t)(kt + i / 24) * CC + i % 24];
        __syncthreads();
        for (int j = 0;; j++) {
            int q = wid + 8 * j; if (q >= 49) break;
            const float* mq = s_m + q * 24;
            for (int kk = lane; kk < KT; kk += 32) {
                const float* kr = s_kv + kk * 24;
                float s = 0.f;
                #pragma unroll
                for (int d = 0; d < 24; d++) s += mq[d] * kr[d];
                prow[(size_t)q * HW + kt + kk] = s;
                lmax[j] = fmaxf(lmax[j], s);
            }
        }
        __syncthreads();
    }
    for (int j = 0;; j++) {
        int q = wid + 8 * j; if (q >= 49) break;
        float v = lmax[j];
        #pragma unroll
        for (int off = 16; off; off >>= 1) v = fmaxf(v, __shfl_xor_sync(0xffffffffu, v, off));
        if (lane == 0) s_max[q] = v;
    }
    __syncthreads();

    for (int j = 0;; j++) {
        int q = wid + 8 * j; if (q >= 49) break;
        float mx = s_max[q]; float sum = 0.f;
        float* pr = prow + (size_t)q * HW;
        for (int kk = lane; kk < HW; kk += 32) {
            float e = expf(pr[kk] - mx);
            pr[kk] = e; sum += e;
        }
        #pragma unroll
        for (int off = 16; off; off >>= 1) sum += __shfl_xor_sync(0xffffffffu, sum, off);
        if (lane == 0) s_sum[q] = sum;
    }
    __syncthreads();

    float acc[5] = {0.f, 0.f, 0.f, 0.f, 0.f};
    for (int kt = 0; kt < HW; kt += KT) {
        for (int i = tid; i < KT * 24; i += 256)
            s_kv[i] = vbase[(size_t)(kt + i / 24) * CC + i % 24];
        for (int i = tid; i < 49 * KT; i += 256) {
            int q = i / KT, kk = i % KT;
            s_pt[i] = prow[(size_t)q * HW + kt + kk];
        }
        __syncthreads();
        #pragma unroll
        for (int r = 0; r < 5; r++) {
            int idx = tid + 256 * r;
            if (idx < 1176) {
                int q = idx / 24, d = idx % 24;
                float a = acc[r];
                const float* pq = s_pt + q * KT;
                #pragma unroll 8
                for (int kk = 0; kk < KT; kk++) a += pq[kk] * s_kv[kk * 24 + d];
                acc[r] = a;
            }
        }
        __syncthreads();
    }
    float* orow = o + (size_t)bh * 49 * 24;
    #pragma unroll
    for (int r = 0; r < 5; r++) {
        int idx = tid + 256 * r;
        if (idx < 1176) orow[idx] = acc[r] / s_sum[idx / 24];
    }
}

// ---------------- bilinear 7->56 upsample ----------------
__global__ void upsample_kernel(const float* __restrict__ o, float* __restrict__ attn)
{
    int x = blockIdx.x, y = blockIdx.y, b = blockIdx.z;
    int c = threadIdx.x;   // 192
    float fy = (y + 0.5f) * 0.125f - 0.5f;
    float fx = (x + 0.5f) * 0.125f - 0.5f;
    int y0 = (int)floorf(fy); float ty = fy - (float)y0;
    int x0 = (int)floorf(fx); float tx = fx - (float)x0;
    int y0c = max(y0, 0), y1c = min(y0 + 1, 6);
    int x0c = max(x0, 0), x1c = min(x0 + 1, 6);

    int h = c / HD2, d = c % HD2;
    const float* ob = o + ((size_t)(b * NHD + h) * 49) * HD2 + d;
    float v00 = ob[(y0c * 7 + x0c) * HD2], v01 = ob[(y0c * 7 + x1c) * HD2];
    float v10 = ob[(y1c * 7 + x0c) * HD2], v11 = ob[(y1c * 7 + x1c) * HD2];
    float v = (1.f - ty) * ((1.f - tx) * v00 + tx * v01) + ty * ((1.f - tx) * v10 + tx * v11);
    attn[(((size_t)b * HH + y) * WW + x) * C2 + c] = v;
}

// ---------------- elementwise concat: [q*a | attn | cut*xe2] ----------------
__global__ void cat_kernel(const float* __restrict__ q, const float* __restrict__ a,
                           const float* __restrict__ attn, const float* __restrict__ cut,
                           const float* __restrict__ xe2, float* __restrict__ cat)
{
    size_t idx = (size_t)blockIdx.x * blockDim.x + threadIdx.x;
    if (idx >= (size_t)MM * 768) return;
    size_t row = idx / 768; int col = (int)(idx % 768);
    float v;
    if (col < 384)      v = q[row * 384 + col] * a[row * 384 + col];
    else if (col < 576) v = attn[row * 192 + col - 384];
    else { size_t off = row * 192 + col - 576; v = cut[off] * xe2[off]; }
    cat[idx] = v;
}

// ---------------- launch ----------------
extern "C" void kernel_launch(void* const* d_in, const int* in_sizes, int n_in,
                              void* d_out, int out_size)
{
    const float* x       = (const float*)d_in[0];
    const float* x_e     = (const float*)d_in[1];
    const float* norm_w  = (const float*)d_in[2];
    const float* norm_b  = (const float*)d_in[3];
    const float* norme_w = (const float*)d_in[4];
    const float* norme_b = (const float*)d_in[5];
    const float* q_w     = (const float*)d_in[6];
    const float* q_b     = (const float*)d_in[7];
    const float* qcut_w  = (const float*)d_in[8];
    const float* qcut_b  = (const float*)d_in[9];
    const float* a_w     = (const float*)d_in[10];
    const float* a_b     = (const float*)d_in[11];
    const float* l_w     = (const float*)d_in[12];
    const float* l_b     = (const float*)d_in[13];
    const float* conv_w  = (const float*)d_in[14];
    const float* conv_b  = (const float*)d_in[15];
    const float* econv_w = (const float*)d_in[16];
    const float* econv_b = (const float*)d_in[17];
    const float* efore_w = (const float*)d_in[18];
    const float* efore_b = (const float*)d_in[19];
    const float* eback_w = (const float*)d_in[20];
    const float* eback_b = (const float*)d_in[21];
    const float* kv_w    = (const float*)d_in[22];
    const float* kv_b    = (const float*)d_in[23];
    const float* scl_w   = (const float*)d_in[24];
    const float* scl_b   = (const float*)d_in[25];
    const float* proj_w  = (const float*)d_in[26];
    const float* proj_b  = (const float*)d_in[27];
    const float* proje_w = (const float*)d_in[28];
    const float* proje_b = (const float*)d_in[29];
    float* out = (float*)d_out;
    float* out_x  = out;
    float* out_xe = out + (size_t)MM * CC;

    float *xn,*xen,*qb,*cutb,*lx,*clx,*ab,*kvb,*ef,*efc,*xe2,*mb,*pb,*ob,*attnb,*catb;
    float *tq,*tl,*ta,*tkv,*tqcut,*tefore,*teback,*tproj,*tproje;
    cudaGetSymbolAddress((void**)&xn,   g_xn);
    cudaGetSymbolAddress((void**)&xen,  g_xen);
    cudaGetSymbolAddress((void**)&qb,   g_q);
    cudaGetSymbolAddress((void**)&cutb, g_cut);
    cudaGetSymbolAddress((void**)&lx,   g_lx);
    cudaGetSymbolAddress((void**)&clx,  g_clx);
    cudaGetSymbolAddress((void**)&ab,   g_a);
    cudaGetSymbolAddress((void**)&kvb,  g_kv);
    cudaGetSymbolAddress((void**)&ef,   g_ef);
    cudaGetSymbolAddress((void**)&efc,  g_efc);
    cudaGetSymbolAddress((void**)&xe2,  g_xe2);
    cudaGetSymbolAddress((void**)&mb,   g_m);
    cudaGetSymbolAddress((void**)&pb,   g_p);
    cudaGetSymbolAddress((void**)&ob,   g_o);
    cudaGetSymbolAddress((void**)&attnb,g_attn);
    cudaGetSymbolAddress((void**)&catb, g_cat);
    cudaGetSymbolAddress((void**)&tq,     g_tq);
    cudaGetSymbolAddress((void**)&tl,     g_tl);
    cudaGetSymbolAddress((void**)&ta,     g_ta);
    cudaGetSymbolAddress((void**)&tkv,    g_tkv);
    cudaGetSymbolAddress((void**)&tqcut,  g_tqcut);
    cudaGetSymbolAddress((void**)&tefore, g_tefore);
    cudaGetSymbolAddress((void**)&teback, g_teback);
    cudaGetSymbolAddress((void**)&tproj,  g_tproj);
    cudaGetSymbolAddress((void**)&tproje, g_tproje);

    cudaFuncSetAttribute(tf32_gemm_kernel, cudaFuncAttributeMaxDynamicSharedMemorySize, GEMM_SMEM);

    // 0) weight transposes (tiny)
    #define TP(src, dst, K_, N_, NP_) \
        transpose_pad_kernel<<<((NP_)*(K_) + 255) / 256, 256>>>(src, dst, K_, N_, NP_)
    TP(q_w,     tq,     384, 384, 384);
    TP(l_w,     tl,     384, 384, 384);
    TP(a_w,     ta,     384, 384, 384);
    TP(kv_w,    tkv,    384, 384, 384);
    TP(qcut_w,  tqcut,  384, 192, 256);
    TP(efore_w, tefore, 192, 192, 256);
    TP(eback_w, teback, 192, 192, 256);
    TP(proj_w,  tproj,  768, 384, 384);
    TP(proje_w, tproje, 768, 192, 256);

    // 1) LayerNorms
    ln_kernel<<<MM, 128>>>(x,   norm_w,  norm_b,  xn,  CC);
    ln_kernel<<<MM, 128>>>(x_e, norme_w, norme_b, xen, C2);

    // 2) pooled shortcut queries -> m (scaled)
    pool_scl_kernel<<<BB * 49, 192>>>(xn, xen, scl_w, scl_b, mb);

    // 3) q / cut / lx(gelu) GEMMs (tf32 tensor cores)
    dim3 gN384(3, MM / 128), gN192(2, MM / 128);
    tf32_gemm_kernel<<<gN384, 256, GEMM_SMEM>>>(xn, tq,    q_b,    qb,   384, 384, 0);
    tf32_gemm_kernel<<<gN192, 256, GEMM_SMEM>>>(xn, tqcut, qcut_b, cutb, 192, 384, 0);
    tf32_gemm_kernel<<<gN384, 256, GEMM_SMEM>>>(xn, tl,    l_b,    lx,   384, 384, 1);

    // 4) depthwise conv on lx, then a / kv GEMMs
    dwconv7_kernel<<<dim3(4, 4, BB * (CC / 8)), 196>>>(lx, conv_w, conv_b, clx, CC);
    tf32_gemm_kernel<<<gN384, 256, GEMM_SMEM>>>(clx, ta,  a_b,  ab,  384, 384, 0);
    tf32_gemm_kernel<<<gN384, 256, GEMM_SMEM>>>(lx,  tkv, kv_b, kvb, 384, 384, 0);

    // 5) attention + bilinear upsample
    attn_kernel<<<BB * NHD, 256>>>(kvb, mb, pb, ob);
    upsample_kernel<<<dim3(WW, HH, BB), C2>>>(ob, attnb);

    // 6) x_e depthwise branch
    tf32_gemm_kernel<<<gN192, 256, GEMM_SMEM>>>(xen, tefore, efore_b, ef, 192, 192, 0);
    dwconv7_kernel<<<dim3(4, 4, BB * (C2 / 8)), 196>>>(ef, econv_w, econv_b, efc, C2);
    tf32_gemm_kernel<<<gN192, 256, GEMM_SMEM>>>(efc, teback, eback_b, xe2, 192, 192, 0);

    // 7) concat + final projections
    size_t tot = (size_t)MM * 768;
    cat_kernel<<<(unsigned)((tot + 255) / 256), 256>>>(qb, ab, attnb, cutb, xe2, catb);
    tf32_gemm_kernel<<<gN384, 256, GEMM_SMEM>>>(catb, tproj,  proj_b,  out_x,  384, 768, 0);
    tf32_gemm_kernel<<<gN192, 256, GEMM_SMEM>>>(catb, tproje, proje_b, out_xe, 192, 768, 0);
}

// round 5
// speedup vs baseline: 3.6212x; 1.0800x over previous
#include <cuda_runtime.h>
#include <math.h>
#include <stdint.h>

// ---------------- problem constants ----------------
#define BB   16
#define HH   56
#define WW   56
#define CC   384
#define C2   192
#define NHD  8
#define HD2  24
#define MM   (BB*HH*WW)        // 50176 tokens
#define HW   (HH*WW)           // 3136
#define KT   112               // attn key tile: 3136 = 28*112
#define SCALE_F 0.20412414523193154f

// ---------------- scratch (device globals; no allocation allowed) ----------------
__device__ float g_xn  [(size_t)MM*CC];
__device__ float g_xen [(size_t)MM*C2];
__device__ float g_q   [(size_t)MM*CC];
__device__ float g_cut [(size_t)MM*C2];
__device__ float g_lx  [(size_t)MM*CC];
__device__ float g_clx [(size_t)MM*CC];
__device__ float g_a   [(size_t)MM*CC];
__device__ float g_kv  [(size_t)MM*CC];
__device__ float g_ef  [(size_t)MM*C2];
__device__ float g_efc [(size_t)MM*C2];
__device__ float g_xe2 [(size_t)MM*C2];
__device__ float g_m   [(size_t)BB*NHD*49*HD2];
__device__ float g_p   [(size_t)BB*NHD*49*HW];
__device__ float g_o   [(size_t)BB*NHD*49*HD2];
__device__ float g_attn[(size_t)MM*C2];
__device__ float g_cat [(size_t)MM*768];

// transposed (+zero-padded) weights, tf32-rounded: Bt[n*K + k] = tf32(W[k*N + n])
__device__ float g_tq    [384*384];
__device__ float g_tl    [384*384];
__device__ float g_ta    [384*384];
__device__ float g_tkv   [384*384];
__device__ float g_tqcut [256*384];
__device__ float g_tefore[256*192];
__device__ float g_teback[256*192];
__device__ float g_tproj [384*768];
__device__ float g_tproje[256*768];

// ---------------- PTX helpers (non-'a' features only: sm_80+ path) ----------------
__device__ __forceinline__ uint32_t smem_u32(const void* p) {
    uint32_t r;
    asm("{ .reg .u64 t; cvta.to.shared.u64 t, %1; cvt.u32.u64 %0, t; }" : "=r"(r) : "l"(p));
    return r;
}
__device__ __forceinline__ void cp_async16(uint32_t dst, const void* src) {
    asm volatile("cp.async.ca.shared.global [%0], [%1], 16;" :: "r"(dst), "l"(src) : "memory");
}
__device__ __forceinline__ void cp_commit() {
    asm volatile("cp.async.commit_group;" ::: "memory");
}
template<int N>
__device__ __forceinline__ void cp_wait() {
    asm volatile("cp.async.wait_group %0;" :: "n"(N) : "memory");
}
__device__ __forceinline__ float round_tf32(float f) {
    uint32_t r;
    asm("cvt.rna.tf32.f32 %0, %1;" : "=r"(r) : "f"(f));
    return __uint_as_float(r);
}
__device__ __forceinline__ void mma_tf32(float* c, const uint32_t* a, uint32_t b0, uint32_t b1) {
    asm volatile(
        "mma.sync.aligned.m16n8k8.row.col.f32.tf32.tf32.f32 "
        "{%0,%1,%2,%3}, {%4,%5,%6,%7}, {%8,%9}, {%0,%1,%2,%3};"
        : "+f"(c[0]), "+f"(c[1]), "+f"(c[2]), "+f"(c[3])
        : "r"(a[0]), "r"(a[1]), "r"(a[2]), "r"(a[3]), "r"(b0), "r"(b1));
}

// ---------------- batched weight transpose + pad + tf32 round (one launch) ----------------
// segment layout (NP*K each), compile-time boundaries
__global__ void transpose_all_kernel(
    const float* __restrict__ q_w,     const float* __restrict__ l_w,
    const float* __restrict__ a_w,     const float* __restrict__ kv_w,
    const float* __restrict__ qcut_w,  const float* __restrict__ efore_w,
    const float* __restrict__ eback_w, const float* __restrict__ proj_w,
    const float* __restrict__ proje_w,
    float* __restrict__ tq,     float* __restrict__ tl,
    float* __restrict__ ta,     float* __restrict__ tkv,
    float* __restrict__ tqcut,  float* __restrict__ tefore,
    float* __restrict__ teback, float* __restrict__ tproj,
    float* __restrict__ tproje)
{
    int idx = blockIdx.x * 256 + threadIdx.x;   // grid exactly 1277952/256 = 4992
    const float* src; float* dst; int K, N, off;
    if      (idx <  147456) { src=q_w;     dst=tq;     K=384; N=384; off=idx; }
    else if (idx <  294912) { src=l_w;     dst=tl;     K=384; N=384; off=idx- 147456; }
    else if (idx <  442368) { src=a_w;     dst=ta;     K=384; N=384; off=idx- 294912; }
    else if (idx <  589824) { src=kv_w;    dst=tkv;    K=384; N=384; off=idx- 442368; }
    else if (idx <  688128) { src=qcut_w;  dst=tqcut;  K=384; N=192; off=idx- 589824; }
    else if (idx <  737280) { src=efore_w; dst=tefore; K=192; N=192; off=idx- 688128; }
    else if (idx <  786432) { src=eback_w; dst=teback; K=192; N=192; off=idx- 737280; }
    else if (idx < 1081344) { src=proj_w;  dst=tproj;  K=768; N=384; off=idx- 786432; }
    else                    { src=proje_w; dst=tproje; K=768; N=192; off=idx-1081344; }
    int n = off / K, k = off % K;
    float v = (n < N) ? src[(size_t)k * N + n] : 0.f;
    dst[off] = round_tf32(v);
}

// ---------------- tf32 tensor-core GEMM: C[M,N] = A[M,K] @ Bt[N,K]^T + bias ----------------
// All A/B inputs are pre-rounded to tf32 -> fragments loaded as raw u32, no cvt in loop.
// act: 0 = none, 1 = exact gelu + tf32-round (for lx which feeds later GEMMs)
#define SSTRIDE 36
#define STAGE_F (128 * SSTRIDE * 2)
#define GEMM_SMEM (2 * STAGE_F * 4)          // 73728 bytes
__global__ __launch_bounds__(256, 2)
void tf32_gemm_kernel(const float* __restrict__ A, const float* __restrict__ Bt,
                      const float* __restrict__ bias, float* __restrict__ C,
                      int N, int K, int act)
{
    extern __shared__ float smf[];
    const int tid  = threadIdx.x;
    const int lane = tid & 31, wid = tid >> 5;
    const int bn = blockIdx.x, bm = blockIdx.y;
    const int warpM = (wid & 3) * 32;
    const int warpN = (wid >> 2) * 64;

    const float* Ab = A  + (size_t)bm * 128 * K;
    const float* Bb = Bt + (size_t)bn * 128 * K;

    uint32_t sb = smem_u32(smf);
    const int ldrow = tid >> 3;
    const int ldcol = (tid & 7) * 4;

    float acc[2][8][4];
    #pragma unroll
    for (int i = 0; i < 2; i++)
        #pragma unroll
        for (int j = 0; j < 8; j++)
            #pragma unroll
            for (int t = 0; t < 4; t++) acc[i][j][t] = 0.f;

    const int NC = K >> 5;

    {
        #pragma unroll
        for (int it = 0; it < 4; it++) {
            int row = ldrow + it * 32;
            uint32_t off = (uint32_t)(row * SSTRIDE + ldcol) * 4;
            cp_async16(sb + off, Ab + (size_t)row * K + ldcol);
            cp_async16(sb + 128 * SSTRIDE * 4 + off, Bb + (size_t)row * K + ldcol);
        }
        cp_commit();
    }

    for (int c = 0; c < NC; c++) {
        int buf = c & 1;
        if (c + 1 < NC) {
            int nbuf = (c + 1) & 1;
            const float* ga = Ab + (c + 1) * 32;
            const float* gb = Bb + (c + 1) * 32;
            uint32_t stage = sb + (uint32_t)nbuf * STAGE_F * 4;
            #pragma unroll
            for (int it = 0; it < 4; it++) {
                int row = ldrow + it * 32;
                uint32_t off = (uint32_t)(row * SSTRIDE + ldcol) * 4;
                cp_async16(stage + off, ga + (size_t)row * K + ldcol);
                cp_async16(stage + 128 * SSTRIDE * 4 + off, gb + (size_t)row * K + ldcol);
            }
            cp_commit();
            cp_wait<1>();
        } else {
            cp_wait<0>();
        }
        __syncthreads();

        const uint32_t* As = (const uint32_t*)(smf + buf * STAGE_F);
        const uint32_t* Bs = As + 128 * SSTRIDE;

        #pragma unroll
        for (int ks = 0; ks < 4; ks++) {
            int k0 = ks * 8 + (lane & 3);
            int rr = lane >> 2;
            uint32_t afr[2][4];
            #pragma unroll
            for (int mt = 0; mt < 2; mt++) {
                int m0 = warpM + mt * 16 + rr;
                afr[mt][0] = As[m0 * SSTRIDE + k0];
                afr[mt][1] = As[(m0 + 8) * SSTRIDE + k0];
                afr[mt][2] = As[m0 * SSTRIDE + k0 + 4];
                afr[mt][3] = As[(m0 + 8) * SSTRIDE + k0 + 4];
            }
            #pragma unroll
            for (int nt = 0; nt < 8; nt++) {
                int n0 = warpN + nt * 8 + rr;
                uint32_t b0 = Bs[n0 * SSTRIDE + k0];
                uint32_t b1 = Bs[n0 * SSTRIDE + k0 + 4];
                mma_tf32(acc[0][nt], afr[0], b0, b1);
                mma_tf32(acc[1][nt], afr[1], b0, b1);
            }
        }
        __syncthreads();
    }

    #pragma unroll
    for (int mt = 0; mt < 2; mt++) {
        size_t row0 = (size_t)bm * 128 + warpM + mt * 16 + (lane >> 2);
        #pragma unroll
        for (int nt = 0; nt < 8; nt++) {
            int gcol = bn * 128 + warpN + nt * 8 + (lane & 3) * 2;
            if (gcol < N) {
                float bs0 = bias[gcol], bs1 = bias[gcol + 1];
                float v0 = acc[mt][nt][0] + bs0;
                float v1 = acc[mt][nt][1] + bs1;
                float v2 = acc[mt][nt][2] + bs0;
                float v3 = acc[mt][nt][3] + bs1;
                if (act == 1) {
                    v0 = round_tf32(0.5f*v0*(1.f+erff(v0*0.70710678118654752f)));
                    v1 = round_tf32(0.5f*v1*(1.f+erff(v1*0.70710678118654752f)));
                    v2 = round_tf32(0.5f*v2*(1.f+erff(v2*0.70710678118654752f)));
                    v3 = round_tf32(0.5f*v3*(1.f+erff(v3*0.70710678118654752f)));
                }
                float2 p0; p0.x = v0; p0.y = v1;
                float2 p1; p1.x = v2; p1.y = v3;
                *(float2*)(C + row0 * (size_t)N + gcol) = p0;
                *(float2*)(C + (row0 + 8) * (size_t)N + gcol) = p1;
            }
        }
    }
}

// ---------------- LayerNorm: one warp per row, output tf32-rounded ----------------
__global__ void ln_kernel(const float* __restrict__ x, const float* __restrict__ w,
                          const float* __restrict__ b, float* __restrict__ out, int C)
{
    int row = blockIdx.x * 8 + (threadIdx.x >> 5);
    int lane = threadIdx.x & 31;
    const float* xr = x + (size_t)row * C;
    float* orow = out + (size_t)row * C;

    int n = C >> 5;               // 12 (C=384) or 6 (C=192)
    float local[12];
    float s = 0.f;
    for (int i = 0; i < n; i++) { float v = xr[lane + 32 * i]; local[i] = v; s += v; }
    #pragma unroll
    for (int o = 16; o; o >>= 1) s += __shfl_xor_sync(0xffffffffu, s, o);
    float mean = s / (float)C;

    float ss = 0.f;
    for (int i = 0; i < n; i++) { float d = local[i] - mean; ss += d * d; }
    #pragma unroll
    for (int o = 16; o; o >>= 1) ss += __shfl_xor_sync(0xffffffffu, ss, o);
    float rstd = rsqrtf(ss / (float)C + 1e-6f);

    for (int i = 0; i < n; i++) {
        int cidx = lane + 32 * i;
        orow[cidx] = round_tf32((local[i] - mean) * rstd * w[cidx] + b[cidx]);
    }
}

// ---------------- pooled shortcut queries + scl GEMM + SCALE fold ----------------
__global__ void pool_scl_kernel(const float* __restrict__ xn, const float* __restrict__ xen,
                                const float* __restrict__ sw, const float* __restrict__ sb,
                                float* __restrict__ mout)
{
    __shared__ float pooled[576];
    int blk = blockIdx.x; int b = blk / 49, qi = blk % 49;
    int py = qi / 7, px = qi % 7;
    int tid = threadIdx.x;    // 192 threads

    for (int ch = tid; ch < 576; ch += 192) {
        float s = 0.f;
        if (ch < CC) {
            const float* base = xn + ((size_t)(b * HH + py * 8) * WW + px * 8) * CC + ch;
            #pragma unroll
            for (int hy = 0; hy < 8; hy++)
                #pragma unroll
                for (int wx = 0; wx < 8; wx++) s += base[(size_t)(hy * WW + wx) * CC];
        } else {
            const float* base = xen + ((size_t)(b * HH + py * 8) * WW + px * 8) * C2 + (ch - CC);
            #pragma unroll
            for (int hy = 0; hy < 8; hy++)
                #pragma unroll
                for (int wx = 0; wx < 8; wx++) s += base[(size_t)(hy * WW + wx) * C2];
        }
        pooled[ch] = s * (1.0f / 64.0f);
    }
    __syncthreads();

    int j = tid;
    float a = sb[j];
    for (int kk = 0; kk < 576; kk++) a += pooled[kk] * sw[(size_t)kk * C2 + j];
    a *= SCALE_F;
    mout[((size_t)(b * NHD + j / HD2) * 49 + qi) * HD2 + (j % HD2)] = a;
}

// ---------------- depthwise 7x7 conv, output tf32-rounded (feeds GEMMs) ----------------
__global__ void dwconv7_kernel(const float* __restrict__ in, const float* __restrict__ w,
                               const float* __restrict__ bias, float* __restrict__ out, int C)
{
    __shared__ float s_in[8][400];
    __shared__ float s_w[8][49];
    __shared__ float s_b[8];
    __shared__ float s_out[196][8];

    int nchunk = C >> 3;
    int b  = blockIdx.z / nchunk;
    int c0 = (blockIdx.z % nchunk) << 3;
    int ty0 = blockIdx.y * 14, tx0 = blockIdx.x * 14;
    int tid = threadIdx.x;   // 196

    for (int idx = tid; idx < 3200; idx += 196) {
        int p = idx >> 3, cc = idx & 7;
        int iy = p / 20, ix = p % 20;
        int gy = ty0 + iy - 3, gx = tx0 + ix - 3;
        float v = 0.f;
        if (gy >= 0 && gy < HH && gx >= 0 && gx < WW)
            v = in[(((size_t)b * HH + gy) * WW + gx) * C + c0 + cc];
        s_in[cc][p] = v;
    }
    for (int idx = tid; idx < 392; idx += 196)
        s_w[idx / 49][idx % 49] = w[(size_t)(c0 + idx / 49) * 49 + idx % 49];
    if (tid < 8) s_b[tid] = bias[c0 + tid];
    __syncthreads();

    int ty = tid / 14, tx = tid % 14;
    float acc[8];
    #pragma unroll
    for (int cc = 0; cc < 8; cc++) acc[cc] = s_b[cc];
    #pragma unroll
    for (int ky = 0; ky < 7; ky++)
        #pragma unroll
        for (int kx = 0; kx < 7; kx++) {
            int p = (ty + ky) * 20 + tx + kx;
            #pragma unroll
            for (int cc = 0; cc < 8; cc++) acc[cc] += s_in[cc][p] * s_w[cc][ky * 7 + kx];
        }
    #pragma unroll
    for (int cc = 0; cc < 8; cc++) s_out[tid][cc] = round_tf32(acc[cc]);
    __syncthreads();

    for (int idx = tid; idx < 1568; idx += 196) {
        int p = idx >> 3, cc = idx & 7;
        int oy = ty0 + p / 14, ox = tx0 + p % 14;
        out[(((size_t)b * HH + oy) * WW + ox) * C + c0 + cc] = s_out[p][cc];
    }
}

// ---------------- attention (KT=112 divides HW exactly) ----------------
__global__ __launch_bounds__(256)
void attn_kernel(const float* __restrict__ kvb, const float* __restrict__ m,
                 float* __restrict__ p, float* __restrict__ o)
{
    __shared__ float s_m[49 * 24];
    __shared__ float s_kv[KT * 24];
    __shared__ float s_pt[49 * KT];
    __shared__ float s_max[49], s_sum[49];

    int bh = blockIdx.x; int b = bh >> 3; int h = bh & 7;
    int tid = threadIdx.x, lane = tid & 31, wid = tid >> 5;

    const float* mrow = m + (size_t)bh * 49 * 24;
    for (int i = tid; i < 1176; i += 256) s_m[i] = mrow[i];
    float* prow = p + (size_t)bh * 49 * HW;
    const float* kbase = kvb + (size_t)b * HW * CC + h * HD2;
    const float* vbase = kbase + C2;

    float lmax[7];
    #pragma unroll
    for (int j = 0; j < 7; j++) lmax[j] = -1e30f;
    __syncthreads();

    for (int kt = 0; kt < HW; kt += KT) {
        for (int i = tid; i < KT * 24; i += 256)
            s_kv[i] = kbase[(size_t)(kt + i / 24) * CC + i % 24];
        __syncthreads();
        for (int j = 0;; j++) {
            int q = wid + 8 * j; if (q >= 49) break;
            const float* mq = s_m + q * 24;
            for (int kk = lane; kk < KT; kk += 32) {
                const float* kr = s_kv + kk * 24;
                float s = 0.f;
                #pragma unroll
                for (int d = 0; d < 24; d++) s += mq[d] * kr[d];
                prow[(size_t)q * HW + kt + kk] = s;
                lmax[j] = fmaxf(lmax[j], s);
            }
        }
        __syncthreads();
    }
    for (int j = 0;; j++) {
        int q = wid + 8 * j; if (q >= 49) break;
        float v = lmax[j];
        #pragma unroll
        for (int off = 16; off; off >>= 1) v = fmaxf(v, __shfl_xor_sync(0xffffffffu, v, off));
        if (lane == 0) s_max[q] = v;
    }
    __syncthreads();

    for (int j = 0;; j++) {
        int q = wid + 8 * j; if (q >= 49) break;
        float mx = s_max[q]; float sum = 0.f;
        float* pr = prow + (size_t)q * HW;
        for (int kk = lane; kk < HW; kk += 32) {
            float e = expf(pr[kk] - mx);
            pr[kk] = e; sum += e;
        }
        #pragma unroll
        for (int off = 16; off; off >>= 1) sum += __shfl_xor_sync(0xffffffffu, sum, off);
        if (lane == 0) s_sum[q] = sum;
    }
    __syncthreads();

    float acc[5] = {0.f, 0.f, 0.f, 0.f, 0.f};
    for (int kt = 0; kt < HW; kt += KT) {
        for (int i = tid; i < KT * 24; i += 256)
            s_kv[i] = vbase[(size_t)(kt + i / 24) * CC + i % 24];
        for (int i = tid; i < 49 * KT; i += 256) {
            int q = i / KT, kk = i % KT;
            s_pt[i] = prow[(size_t)q * HW + kt + kk];
        }
        __syncthreads();
        #pragma unroll
        for (int r = 0; r < 5; r++) {
            int idx = tid + 256 * r;
            if (idx < 1176) {
                int q = idx / 24, d = idx % 24;
                float a = acc[r];
                const float* pq = s_pt + q * KT;
                #pragma unroll 8
                for (int kk = 0; kk < KT; kk++) a += pq[kk] * s_kv[kk * 24 + d];
                acc[r] = a;
            }
        }
        __syncthreads();
    }
    float* orow = o + (size_t)bh * 49 * 24;
    #pragma unroll
    for (int r = 0; r < 5; r++) {
        int idx = tid + 256 * r;
        if (idx < 1176) orow[idx] = acc[r] / s_sum[idx / 24];
    }
}

// ---------------- bilinear 7->56 upsample ----------------
__global__ void upsample_kernel(const float* __restrict__ o, float* __restrict__ attn)
{
    int x = blockIdx.x, y = blockIdx.y, b = blockIdx.z;
    int c = threadIdx.x;   // 192
    float fy = (y + 0.5f) * 0.125f - 0.5f;
    float fx = (x + 0.5f) * 0.125f - 0.5f;
    int y0 = (int)floorf(fy); float ty = fy - (float)y0;
    int x0 = (int)floorf(fx); float tx = fx - (float)x0;
    int y0c = max(y0, 0), y1c = min(y0 + 1, 6);
    int x0c = max(x0, 0), x1c = min(x0 + 1, 6);

    int h = c / HD2, d = c % HD2;
    const float* ob = o + ((size_t)(b * NHD + h) * 49) * HD2 + d;
    float v00 = ob[(y0c * 7 + x0c) * HD2], v01 = ob[(y0c * 7 + x1c) * HD2];
    float v10 = ob[(y1c * 7 + x0c) * HD2], v11 = ob[(y1c * 7 + x1c) * HD2];
    float v = (1.f - ty) * ((1.f - tx) * v00 + tx * v01) + ty * ((1.f - tx) * v10 + tx * v11);
    attn[(((size_t)b * HH + y) * WW + x) * C2 + c] = v;
}

// ---------------- concat [q*a | attn | cut*xe2], row-per-block, float4, tf32-rounded ----------------
__global__ void cat_kernel(const float* __restrict__ q, const float* __restrict__ a,
                           const float* __restrict__ attn, const float* __restrict__ cut,
                           const float* __restrict__ xe2, float* __restrict__ cat)
{
    size_t row = blockIdx.x;
    int t = threadIdx.x;                 // 192 threads, 4 floats each
    float4 v;
    if (t < 96) {
        int c = t * 4;
        float4 vq = *(const float4*)(q + row * 384 + c);
        float4 va = *(const float4*)(a + row * 384 + c);
        v.x = vq.x * va.x; v.y = vq.y * va.y; v.z = vq.z * va.z; v.w = vq.w * va.w;
    } else if (t < 144) {
        int c = (t - 96) * 4;
        v = *(const float4*)(attn + row * 192 + c);
    } else {
        int c = (t - 144) * 4;
        float4 vc = *(const float4*)(cut + row * 192 + c);
        float4 vx = *(const float4*)(xe2 + row * 192 + c);
        v.x = vc.x * vx.x; v.y = vc.y * vx.y; v.z = vc.z * vx.z; v.w = vc.w * vx.w;
    }
    v.x = round_tf32(v.x); v.y = round_tf32(v.y);
    v.z = round_tf32(v.z); v.w = round_tf32(v.w);
    *(float4*)(cat + row * 768 + t * 4) = v;
}

// ---------------- launch ----------------
extern "C" void kernel_launch(void* const* d_in, const int* in_sizes, int n_in,
                              void* d_out, int out_size)
{
    const float* x       = (const float*)d_in[0];
    const float* x_e     = (const float*)d_in[1];
    const float* norm_w  = (const float*)d_in[2];
    const float* norm_b  = (const float*)d_in[3];
    const float* norme_w = (const float*)d_in[4];
    const float* norme_b = (const float*)d_in[5];
    const float* q_w     = (const float*)d_in[6];
    const float* q_b     = (const float*)d_in[7];
    const float* qcut_w  = (const float*)d_in[8];
    const float* qcut_b  = (const float*)d_in[9];
    const float* a_w     = (const float*)d_in[10];
    const float* a_b     = (const float*)d_in[11];
    const float* l_w     = (const float*)d_in[12];
    const float* l_b     = (const float*)d_in[13];
    const float* conv_w  = (const float*)d_in[14];
    const float* conv_b  = (const float*)d_in[15];
    const float* econv_w = (const float*)d_in[16];
    const float* econv_b = (const float*)d_in[17];
    const float* efore_w = (const float*)d_in[18];
    const float* efore_b = (const float*)d_in[19];
    const float* eback_w = (const float*)d_in[20];
    const float* eback_b = (const float*)d_in[21];
    const float* kv_w    = (const float*)d_in[22];
    const float* kv_b    = (const float*)d_in[23];
    const float* scl_w   = (const float*)d_in[24];
    const float* scl_b   = (const float*)d_in[25];
    const float* proj_w  = (const float*)d_in[26];
    const float* proj_b  = (const float*)d_in[27];
    const float* proje_w = (const float*)d_in[28];
    const float* proje_b = (const float*)d_in[29];
    float* out = (float*)d_out;
    float* out_x  = out;
    float* out_xe = out + (size_t)MM * CC;

    float *xn,*xen,*qb,*cutb,*lx,*clx,*ab,*kvb,*ef,*efc,*xe2,*mb,*pb,*ob,*attnb,*catb;
    float *tq,*tl,*ta,*tkv,*tqcut,*tefore,*teback,*tproj,*tproje;
    cudaGetSymbolAddress((void**)&xn,   g_xn);
    cudaGetSymbolAddress((void**)&xen,  g_xen);
    cudaGetSymbolAddress((void**)&qb,   g_q);
    cudaGetSymbolAddress((void**)&cutb, g_cut);
    cudaGetSymbolAddress((void**)&lx,   g_lx);
    cudaGetSymbolAddress((void**)&clx,  g_clx);
    cudaGetSymbolAddress((void**)&ab,   g_a);
    cudaGetSymbolAddress((void**)&kvb,  g_kv);
    cudaGetSymbolAddress((void**)&ef,   g_ef);
    cudaGetSymbolAddress((void**)&efc,  g_efc);
    cudaGetSymbolAddress((void**)&xe2,  g_xe2);
    cudaGetSymbolAddress((void**)&mb,   g_m);
    cudaGetSymbolAddress((void**)&pb,   g_p);
    cudaGetSymbolAddress((void**)&ob,   g_o);
    cudaGetSymbolAddress((void**)&attnb,g_attn);
    cudaGetSymbolAddress((void**)&catb, g_cat);
    cudaGetSymbolAddress((void**)&tq,     g_tq);
    cudaGetSymbolAddress((void**)&tl,     g_tl);
    cudaGetSymbolAddress((void**)&ta,     g_ta);
    cudaGetSymbolAddress((void**)&tkv,    g_tkv);
    cudaGetSymbolAddress((void**)&tqcut,  g_tqcut);
    cudaGetSymbolAddress((void**)&tefore, g_tefore);
    cudaGetSymbolAddress((void**)&teback, g_teback);
    cudaGetSymbolAddress((void**)&tproj,  g_tproj);
    cudaGetSymbolAddress((void**)&tproje, g_tproje);

    cudaFuncSetAttribute(tf32_gemm_kernel, cudaFuncAttributeMaxDynamicSharedMemorySize, GEMM_SMEM);

    // 0) all weight transposes in one launch
    transpose_all_kernel<<<4992, 256>>>(q_w, l_w, a_w, kv_w, qcut_w, efore_w, eback_w,
                                        proj_w, proje_w,
                                        tq, tl, ta, tkv, tqcut, tefore, teback, tproj, tproje);

    // 1) LayerNorms (warp per row)
    ln_kernel<<<MM / 8, 256>>>(x,   norm_w,  norm_b,  xn,  CC);
    ln_kernel<<<MM / 8, 256>>>(x_e, norme_w, norme_b, xen, C2);

    // 2) pooled shortcut queries -> m (scaled)
    pool_scl_kernel<<<BB * 49, 192>>>(xn, xen, scl_w, scl_b, mb);

    // 3) q / cut / lx(gelu) GEMMs (tf32 tensor cores)
    dim3 gN384(3, MM / 128), gN192(2, MM / 128);
    tf32_gemm_kernel<<<gN384, 256, GEMM_SMEM>>>(xn, tq,    q_b,    qb,   384, 384, 0);
    tf32_gemm_kernel<<<gN192, 256, GEMM_SMEM>>>(xn, tqcut, qcut_b, cutb, 192, 384, 0);
    tf32_gemm_kernel<<<gN384, 256, GEMM_SMEM>>>(xn, tl,    l_b,    lx,   384, 384, 1);

    // 4) depthwise conv on lx, then a / kv GEMMs
    dwconv7_kernel<<<dim3(4, 4, BB * (CC / 8)), 196>>>(lx, conv_w, conv_b, clx, CC);
    tf32_gemm_kernel<<<gN384, 256, GEMM_SMEM>>>(clx, ta,  a_b,  ab,  384, 384, 0);
    tf32_gemm_kernel<<<gN384, 256, GEMM_SMEM>>>(lx,  tkv, kv_b, kvb, 384, 384, 0);

    // 5) attention + bilinear upsample
    attn_kernel<<<BB * NHD, 256>>>(kvb, mb, pb, ob);
    upsample_kernel<<<dim3(WW, HH, BB), C2>>>(ob, attnb);

    // 6) x_e depthwise branch
    tf32_gemm_kernel<<<gN192, 256, GEMM_SMEM>>>(xen, tefore, efore_b, ef, 192, 192, 0);
    dwconv7_kernel<<<dim3(4, 4, BB * (C2 / 8)), 196>>>(ef, econv_w, econv_b, efc, C2);
    tf32_gemm_kernel<<<gN192, 256, GEMM_SMEM>>>(efc, teback, eback_b, xe2, 192, 192, 0);

    // 7) concat + final projections
    cat_kernel<<<MM, 192>>>(qb, ab, attnb, cutb, xe2, catb);
    tf32_gemm_kernel<<<gN384, 256, GEMM_SMEM>>>(catb, tproj,  proj_b,  out_x,  384, 768, 0);
    tf32_gemm_kernel<<<gN192, 256, GEMM_SMEM>>>(catb, tproje, proje_b, out_xe, 192, 768, 0);
}

// round 6
// speedup vs baseline: 4.6959x; 1.2968x over previous
#include <cuda_runtime.h>
#include <cuda_fp16.h>
#include <math.h>
#include <stdint.h>

// ---------------- problem constants ----------------
#define BB   16
#define HH   56
#define WW   56
#define CC   384
#define C2   192
#define NHD  8
#define HD2  24
#define MM   (BB*HH*WW)        // 50176 tokens
#define HW   (HH*WW)           // 3136
#define KT   112               // attn key tile: 3136 = 28*112
#define SCALE_F 0.20412414523193154f

// ---------------- scratch (device globals; no allocation allowed) ----------------
__device__ __align__(16) __half g_xn  [(size_t)MM*CC];
__device__ __align__(16) __half g_xen [(size_t)MM*C2];
__device__ __align__(16) __half g_q   [(size_t)MM*CC];
__device__ __align__(16) __half g_cut [(size_t)MM*C2];
__device__ __align__(16) __half g_lx  [(size_t)MM*CC];
__device__ __align__(16) __half g_clx [(size_t)MM*CC];
__device__ __align__(16) __half g_a   [(size_t)MM*CC];
__device__ float  g_kv  [(size_t)MM*CC];          // attn input stays fp32
__device__ __align__(16) __half g_ef  [(size_t)MM*C2];
__device__ __align__(16) __half g_efc [(size_t)MM*C2];
__device__ __align__(16) __half g_xe2 [(size_t)MM*C2];
__device__ float  g_m   [(size_t)BB*NHD*49*HD2];
__device__ float  g_p   [(size_t)BB*NHD*49*HW];
__device__ float  g_o   [(size_t)BB*NHD*49*HD2];
__device__ __align__(16) __half g_attn[(size_t)MM*C2];
__device__ __align__(16) __half g_cat [(size_t)MM*768];

// transposed (+zero-padded) weights, fp16: Bt[n*K + k] = h(W[k*N + n])
__device__ __align__(16) __half g_tq    [384*384];
__device__ __align__(16) __half g_tl    [384*384];
__device__ __align__(16) __half g_ta    [384*384];
__device__ __align__(16) __half g_tkv   [384*384];
__device__ __align__(16) __half g_tqcut [256*384];
__device__ __align__(16) __half g_tefore[256*192];
__device__ __align__(16) __half g_teback[256*192];
__device__ __align__(16) __half g_tproj [384*768];
__device__ __align__(16) __half g_tproje[256*768];

// ---------------- PTX helpers (sm_80+ features only; no 'a'-gated instrs) ----------------
__device__ __forceinline__ uint32_t smem_u32(const void* p) {
    uint32_t r;
    asm("{ .reg .u64 t; cvta.to.shared.u64 t, %1; cvt.u32.u64 %0, t; }" : "=r"(r) : "l"(p));
    return r;
}
__device__ __forceinline__ void cp_async16(uint32_t dst, const void* src) {
    asm volatile("cp.async.ca.shared.global [%0], [%1], 16;" :: "r"(dst), "l"(src) : "memory");
}
__device__ __forceinline__ void cp_commit() {
    asm volatile("cp.async.commit_group;" ::: "memory");
}
template<int N>
__device__ __forceinline__ void cp_wait() {
    asm volatile("cp.async.wait_group %0;" :: "n"(N) : "memory");
}
__device__ __forceinline__ void ldsm_x4(uint32_t& r0, uint32_t& r1, uint32_t& r2, uint32_t& r3,
                                        uint32_t addr) {
    asm volatile("ldmatrix.sync.aligned.m8n8.x4.shared.b16 {%0,%1,%2,%3}, [%4];"
                 : "=r"(r0), "=r"(r1), "=r"(r2), "=r"(r3) : "r"(addr));
}
__device__ __forceinline__ void mma_f16(float* c, const uint32_t* a, uint32_t b0, uint32_t b1) {
    asm volatile(
        "mma.sync.aligned.m16n8k16.row.col.f32.f16.f16.f32 "
        "{%0,%1,%2,%3}, {%4,%5,%6,%7}, {%8,%9}, {%0,%1,%2,%3};"
        : "+f"(c[0]), "+f"(c[1]), "+f"(c[2]), "+f"(c[3])
        : "r"(a[0]), "r"(a[1]), "r"(a[2]), "r"(a[3]), "r"(b0), "r"(b1));
}

// ---------------- batched weight transpose + pad + fp16 (one launch) ----------------
__global__ void transpose_all_kernel(
    const float* __restrict__ q_w,     const float* __restrict__ l_w,
    const float* __restrict__ a_w,     const float* __restrict__ kv_w,
    const float* __restrict__ qcut_w,  const float* __restrict__ efore_w,
    const float* __restrict__ eback_w, const float* __restrict__ proj_w,
    const float* __restrict__ proje_w,
    __half* __restrict__ tq,     __half* __restrict__ tl,
    __half* __restrict__ ta,     __half* __restrict__ tkv,
    __half* __restrict__ tqcut,  __half* __restrict__ tefore,
    __half* __restrict__ teback, __half* __restrict__ tproj,
    __half* __restrict__ tproje)
{
    int idx = blockIdx.x * 256 + threadIdx.x;   // grid exactly 1277952/256 = 4992
    const float* src; __half* dst; int K, N, off;
    if      (idx <  147456) { src=q_w;     dst=tq;     K=384; N=384; off=idx; }
    else if (idx <  294912) { src=l_w;     dst=tl;     K=384; N=384; off=idx- 147456; }
    else if (idx <  442368) { src=a_w;     dst=ta;     K=384; N=384; off=idx- 294912; }
    else if (idx <  589824) { src=kv_w;    dst=tkv;    K=384; N=384; off=idx- 442368; }
    else if (idx <  688128) { src=qcut_w;  dst=tqcut;  K=384; N=192; off=idx- 589824; }
    else if (idx <  737280) { src=efore_w; dst=tefore; K=192; N=192; off=idx- 688128; }
    else if (idx <  786432) { src=eback_w; dst=teback; K=192; N=192; off=idx- 737280; }
    else if (idx < 1081344) { src=proj_w;  dst=tproj;  K=768; N=384; off=idx- 786432; }
    else                    { src=proje_w; dst=tproje; K=768; N=192; off=idx-1081344; }
    int n = off / K, k = off % K;
    float v = (n < N) ? src[(size_t)k * N + n] : 0.f;
    dst[off] = __float2half(v);
}

// ---------------- fp16 tensor-core GEMM: C[M,N] = A[M,K] @ Bt[N,K]^T + bias ----------------
// 128x128 CTA tile, BK=64 halves, cp.async double buffer, ldmatrix fragments.
// 8 warps x (32x64) warp tiles. smem row stride 72 halves (144 B): ldmatrix phase
// covers 8 rows at 16B-chunk indices 9r mod 8 = r -> conflict-free.
// Output: Ch!=null -> half, else float (Cf). act=1: exact gelu.
#define SSH 72
#define STAGE_BYTES (128 * SSH * 2 * 2)     // A+B per stage = 36864 B
#define GEMM_SMEM (2 * STAGE_BYTES)         // 73728 B
__global__ __launch_bounds__(256, 2)
void h16_gemm_kernel(const __half* __restrict__ A, const __half* __restrict__ Bt,
                     const float* __restrict__ bias, float* __restrict__ Cf,
                     __half* __restrict__ Ch, int N, int K, int act)
{
    extern __shared__ __half smh[];
    const int tid = threadIdx.x, lane = tid & 31, wid = tid >> 5;
    const int bn = blockIdx.x, bm = blockIdx.y;
    const int warpM = (wid & 3) * 32, warpN = (wid >> 2) * 64;

    const __half* Ab = A  + (size_t)bm * 128 * K;
    const __half* Bb = Bt + (size_t)bn * 128 * K;
    uint32_t sb = smem_u32(smh);
    const int ldrow = tid >> 3;          // 0..31 (+32 per it)
    const int ldch  = tid & 7;           // 16B chunk within 128B row

    float acc[2][8][4];
    #pragma unroll
    for (int i = 0; i < 2; i++)
        #pragma unroll
        for (int j = 0; j < 8; j++)
            #pragma unroll
            for (int t = 0; t < 4; t++) acc[i][j][t] = 0.f;

    const int NC = K >> 6;

    // ldmatrix lane-address constants
    const uint32_t aoff = (uint32_t)((lane & 7) + ((lane >> 3) & 1) * 8) * 144 + (lane >> 4) * 16;
    const uint32_t boff = (uint32_t)((lane & 7) + (lane >> 4) * 8) * 144 + ((lane >> 3) & 1) * 16;

    // prefetch chunk 0 into stage 0
    #pragma unroll
    for (int it = 0; it < 4; it++) {
        int row = ldrow + it * 32;
        uint32_t o = (uint32_t)row * 144 + ldch * 16;
        cp_async16(sb + o, Ab + (size_t)row * K + ldch * 8);
        cp_async16(sb + 128 * SSH * 2 + o, Bb + (size_t)row * K + ldch * 8);
    }
    cp_commit();

    for (int c = 0; c < NC; c++) {
        int buf = c & 1;
        if (c + 1 < NC) {
            uint32_t stage = sb + (uint32_t)((c + 1) & 1) * STAGE_BYTES;
            const __half* ga = Ab + (c + 1) * 64;
            const __half* gb = Bb + (c + 1) * 64;
            #pragma unroll
            for (int it = 0; it < 4; it++) {
                int row = ldrow + it * 32;
                uint32_t o = (uint32_t)row * 144 + ldch * 16;
                cp_async16(stage + o, ga + (size_t)row * K + ldch * 8);
                cp_async16(stage + 128 * SSH * 2 + o, gb + (size_t)row * K + ldch * 8);
            }
            cp_commit();
            cp_wait<1>();
        } else {
            cp_wait<0>();
        }
        __syncthreads();

        uint32_t sA = sb + (uint32_t)buf * STAGE_BYTES + (uint32_t)warpM * 144 + aoff;
        uint32_t sBv = sb + (uint32_t)buf * STAGE_BYTES + 128 * SSH * 2 + (uint32_t)warpN * 144 + boff;

        #pragma unroll
        for (int ks = 0; ks < 4; ks++) {
            uint32_t afr[2][4];
            ldsm_x4(afr[0][0], afr[0][1], afr[0][2], afr[0][3], sA + ks * 32);
            ldsm_x4(afr[1][0], afr[1][1], afr[1][2], afr[1][3], sA + 16 * 144 + ks * 32);
            #pragma unroll
            for (int ntp = 0; ntp < 4; ntp++) {
                uint32_t b0, b1, b2, b3;
                ldsm_x4(b0, b1, b2, b3, sBv + (uint32_t)ntp * 16 * 144 + ks * 32);
                mma_f16(acc[0][ntp * 2],     afr[0], b0, b1);
                mma_f16(acc[1][ntp * 2],     afr[1], b0, b1);
                mma_f16(acc[0][ntp * 2 + 1], afr[0], b2, b3);
                mma_f16(acc[1][ntp * 2 + 1], afr[1], b2, b3);
            }
        }
        __syncthreads();
    }

    #pragma unroll
    for (int mt = 0; mt < 2; mt++) {
        size_t row0 = (size_t)bm * 128 + warpM + mt * 16 + (lane >> 2);
        #pragma unroll
        for (int nt = 0; nt < 8; nt++) {
            int gcol = bn * 128 + warpN + nt * 8 + (lane & 3) * 2;
            if (gcol < N) {
                float bs0 = bias[gcol], bs1 = bias[gcol + 1];
                float v0 = acc[mt][nt][0] + bs0;
                float v1 = acc[mt][nt][1] + bs1;
                float v2 = acc[mt][nt][2] + bs0;
                float v3 = acc[mt][nt][3] + bs1;
                if (act == 1) {
                    v0 = 0.5f*v0*(1.f+erff(v0*0.70710678118654752f));
                    v1 = 0.5f*v1*(1.f+erff(v1*0.70710678118654752f));
                    v2 = 0.5f*v2*(1.f+erff(v2*0.70710678118654752f));
                    v3 = 0.5f*v3*(1.f+erff(v3*0.70710678118654752f));
                }
                if (Ch) {
                    __half2 h0; h0.x = __float2half(v0); h0.y = __float2half(v1);
                    __half2 h1; h1.x = __float2half(v2); h1.y = __float2half(v3);
                    *(__half2*)(Ch + row0 * (size_t)N + gcol) = h0;
                    *(__half2*)(Ch + (row0 + 8) * (size_t)N + gcol) = h1;
                } else {
                    float2 p0; p0.x = v0; p0.y = v1;
                    float2 p1; p1.x = v2; p1.y = v3;
                    *(float2*)(Cf + row0 * (size_t)N + gcol) = p0;
                    *(float2*)(Cf + (row0 + 8) * (size_t)N + gcol) = p1;
                }
            }
        }
    }
}

// ---------------- LayerNorm: one warp per row, fp16 output ----------------
__global__ void ln_kernel(const float* __restrict__ x, const float* __restrict__ w,
                          const float* __restrict__ b, __half* __restrict__ out, int C)
{
    int row = blockIdx.x * 8 + (threadIdx.x >> 5);
    int lane = threadIdx.x & 31;
    const float* xr = x + (size_t)row * C;
    __half* orow = out + (size_t)row * C;

    int n = C >> 5;
    float local[12];
    float s = 0.f;
    for (int i = 0; i < n; i++) { float v = xr[lane + 32 * i]; local[i] = v; s += v; }
    #pragma unroll
    for (int o = 16; o; o >>= 1) s += __shfl_xor_sync(0xffffffffu, s, o);
    float mean = s / (float)C;

    float ss = 0.f;
    for (int i = 0; i < n; i++) { float d = local[i] - mean; ss += d * d; }
    #pragma unroll
    for (int o = 16; o; o >>= 1) ss += __shfl_xor_sync(0xffffffffu, ss, o);
    float rstd = rsqrtf(ss / (float)C + 1e-6f);

    for (int i = 0; i < n; i++) {
        int cidx = lane + 32 * i;
        orow[cidx] = __float2half((local[i] - mean) * rstd * w[cidx] + b[cidx]);
    }
}

// ---------------- pooled shortcut queries + scl GEMM + SCALE fold ----------------
__global__ void pool_scl_kernel(const __half* __restrict__ xn, const __half* __restrict__ xen,
                                const float* __restrict__ sw, const float* __restrict__ sb,
                                float* __restrict__ mout)
{
    __shared__ float pooled[576];
    int blk = blockIdx.x; int b = blk / 49, qi = blk % 49;
    int py = qi / 7, px = qi % 7;
    int tid = threadIdx.x;    // 192 threads

    for (int ch = tid; ch < 576; ch += 192) {
        float s = 0.f;
        if (ch < CC) {
            const __half* base = xn + ((size_t)(b * HH + py * 8) * WW + px * 8) * CC + ch;
            #pragma unroll
            for (int hy = 0; hy < 8; hy++)
                #pragma unroll
                for (int wx = 0; wx < 8; wx++) s += __half2float(base[(size_t)(hy * WW + wx) * CC]);
        } else {
            const __half* base = xen + ((size_t)(b * HH + py * 8) * WW + px * 8) * C2 + (ch - CC);
            #pragma unroll
            for (int hy = 0; hy < 8; hy++)
                #pragma unroll
                for (int wx = 0; wx < 8; wx++) s += __half2float(base[(size_t)(hy * WW + wx) * C2]);
        }
        pooled[ch] = s * (1.0f / 64.0f);
    }
    __syncthreads();

    int j = tid;
    float a = sb[j];
    for (int kk = 0; kk < 576; kk++) a += pooled[kk] * sw[(size_t)kk * C2 + j];
    a *= SCALE_F;
    mout[((size_t)(b * NHD + j / HD2) * 49 + qi) * HD2 + (j % HD2)] = a;
}

// ---------------- depthwise 7x7 conv, half in / half out (fp32 math) ----------------
__global__ void dwconv7_kernel(const __half* __restrict__ in, const float* __restrict__ w,
                               const float* __restrict__ bias, __half* __restrict__ out, int C)
{
    __shared__ float s_in[8][400];
    __shared__ float s_w[8][49];
    __shared__ float s_b[8];
    __shared__ __half s_out[196][8];

    int nchunk = C >> 3;
    int b  = blockIdx.z / nchunk;
    int c0 = (blockIdx.z % nchunk) << 3;
    int ty0 = blockIdx.y * 14, tx0 = blockIdx.x * 14;
    int tid = threadIdx.x;   // 196

    for (int idx = tid; idx < 3200; idx += 196) {
        int p = idx >> 3, cc = idx & 7;
        int iy = p / 20, ix = p % 20;
        int gy = ty0 + iy - 3, gx = tx0 + ix - 3;
        float v = 0.f;
        if (gy >= 0 && gy < HH && gx >= 0 && gx < WW)
            v = __half2float(in[(((size_t)b * HH + gy) * WW + gx) * C + c0 + cc]);
        s_in[cc][p] = v;
    }
    for (int idx = tid; idx < 392; idx += 196)
        s_w[idx / 49][idx % 49] = w[(size_t)(c0 + idx / 49) * 49 + idx % 49];
    if (tid < 8) s_b[tid] = bias[c0 + tid];
    __syncthreads();

    int ty = tid / 14, tx = tid % 14;
    float acc[8];
    #pragma unroll
    for (int cc = 0; cc < 8; cc++) acc[cc] = s_b[cc];
    #pragma unroll
    for (int ky = 0; ky < 7; ky++)
        #pragma unroll
        for (int kx = 0; kx < 7; kx++) {
            int p = (ty + ky) * 20 + tx + kx;
            #pragma unroll
            for (int cc = 0; cc < 8; cc++) acc[cc] += s_in[cc][p] * s_w[cc][ky * 7 + kx];
        }
    #pragma unroll
    for (int cc = 0; cc < 8; cc++) s_out[tid][cc] = __float2half(acc[cc]);
    __syncthreads();

    for (int idx = tid; idx < 1568; idx += 196) {
        int p = idx >> 3, cc = idx & 7;
        int oy = ty0 + p / 14, ox = tx0 + p % 14;
        out[(((size_t)b * HH + oy) * WW + ox) * C + c0 + cc] = s_out[p][cc];
    }
}

// ---------------- attention (unchanged fp32 path; KT=112 divides HW) ----------------
__global__ __launch_bounds__(256)
void attn_kernel(const float* __restrict__ kvb, const float* __restrict__ m,
                 float* __restrict__ p, float* __restrict__ o)
{
    __shared__ float s_m[49 * 24];
    __shared__ float s_kv[KT * 24];
    __shared__ float s_pt[49 * KT];
    __shared__ float s_max[49], s_sum[49];

    int bh = blockIdx.x; int b = bh >> 3; int h = bh & 7;
    int tid = threadIdx.x, lane = tid & 31, wid = tid >> 5;

    const float* mrow = m + (size_t)bh * 49 * 24;
    for (int i = tid; i < 1176; i += 256) s_m[i] = mrow[i];
    float* prow = p + (size_t)bh * 49 * HW;
    const float* kbase = kvb + (size_t)b * HW * CC + h * HD2;
    const float* vbase = kbase + C2;

    float lmax[7];
    #pragma unroll
    for (int j = 0; j < 7; j++) lmax[j] = -1e30f;
    __syncthreads();

    for (int kt = 0; kt < HW; kt += KT) {
        for (int i = tid; i < KT * 24; i += 256)
            s_kv[i] = kbase[(size_t)(kt + i / 24) * CC + i % 24];
        __syncthreads();
        for (int j = 0;; j++) {
            int q = wid + 8 * j; if (q >= 49) break;
            const float* mq = s_m + q * 24;
            for (int kk = lane; kk < KT; kk += 32) {
                const float* kr = s_kv + kk * 24;
                float s = 0.f;
                #pragma unroll
                for (int d = 0; d < 24; d++) s += mq[d] * kr[d];
                prow[(size_t)q * HW + kt + kk] = s;
                lmax[j] = fmaxf(lmax[j], s);
            }
        }
        __syncthreads();
    }
    for (int j = 0;; j++) {
        int q = wid + 8 * j; if (q >= 49) break;
        float v = lmax[j];
        #pragma unroll
        for (int off = 16; off; off >>= 1) v = fmaxf(v, __shfl_xor_sync(0xffffffffu, v, off));
        if (lane == 0) s_max[q] = v;
    }
    __syncthreads();

    for (int j = 0;; j++) {
        int q = wid + 8 * j; if (q >= 49) break;
        float mx = s_max[q]; float sum = 0.f;
        float* pr = prow + (size_t)q * HW;
        for (int kk = lane; kk < HW; kk += 32) {
            float e = expf(pr[kk] - mx);
            pr[kk] = e; sum += e;
        }
        #pragma unroll
        for (int off = 16; off; off >>= 1) sum += __shfl_xor_sync(0xffffffffu, sum, off);
        if (lane == 0) s_sum[q] = sum;
    }
    __syncthreads();

    float acc[5] = {0.f, 0.f, 0.f, 0.f, 0.f};
    for (int kt = 0; kt < HW; kt += KT) {
        for (int i = tid; i < KT * 24; i += 256)
            s_kv[i] = vbase[(size_t)(kt + i / 24) * CC + i % 24];
        for (int i = tid; i < 49 * KT; i += 256) {
            int q = i / KT, kk = i % KT;
            s_pt[i] = prow[(size_t)q * HW + kt + kk];
        }
        __syncthreads();
        #pragma unroll
        for (int r = 0; r < 5; r++) {
            int idx = tid + 256 * r;
            if (idx < 1176) {
                int q = idx / 24, d = idx % 24;
                float a = acc[r];
                const float* pq = s_pt + q * KT;
                #pragma unroll 8
                for (int kk = 0; kk < KT; kk++) a += pq[kk] * s_kv[kk * 24 + d];
                acc[r] = a;
            }
        }
        __syncthreads();
    }
    float* orow = o + (size_t)bh * 49 * 24;
    #pragma unroll
    for (int r = 0; r < 5; r++) {
        int idx = tid + 256 * r;
        if (idx < 1176) orow[idx] = acc[r] / s_sum[idx / 24];
    }
}

// ---------------- bilinear 7->56 upsample, half output ----------------
__global__ void upsample_kernel(const float* __restrict__ o, __half* __restrict__ attn)
{
    int x = blockIdx.x, y = blockIdx.y, b = blockIdx.z;
    int c = threadIdx.x;   // 192
    float fy = (y + 0.5f) * 0.125f - 0.5f;
    float fx = (x + 0.5f) * 0.125f - 0.5f;
    int y0 = (int)floorf(fy); float ty = fy - (float)y0;
    int x0 = (int)floorf(fx); float tx = fx - (float)x0;
    int y0c = max(y0, 0), y1c = min(y0 + 1, 6);
    int x0c = max(x0, 0), x1c = min(x0 + 1, 6);

    int h = c / HD2, d = c % HD2;
    const float* ob = o + ((size_t)(b * NHD + h) * 49) * HD2 + d;
    float v00 = ob[(y0c * 7 + x0c) * HD2], v01 = ob[(y0c * 7 + x1c) * HD2];
    float v10 = ob[(y1c * 7 + x0c) * HD2], v11 = ob[(y1c * 7 + x1c) * HD2];
    float v = (1.f - ty) * ((1.f - tx) * v00 + tx * v01) + ty * ((1.f - tx) * v10 + tx * v11);
    attn[(((size_t)b * HH + y) * WW + x) * C2 + c] = __float2half(v);
}

// ---------------- concat [q*a | attn | cut*xe2], half in/out ----------------
__global__ void cat_kernel(const __half* __restrict__ q, const __half* __restrict__ a,
                           const __half* __restrict__ attn, const __half* __restrict__ cut,
                           const __half* __restrict__ xe2, __half* __restrict__ cat)
{
    size_t row = blockIdx.x;
    int t = threadIdx.x;                 // 192 threads, 4 halves each
    __half v[4];
    if (t < 96) {
        int c = t * 4;
        #pragma unroll
        for (int j = 0; j < 4; j++)
            v[j] = __float2half(__half2float(q[row * 384 + c + j]) *
                                __half2float(a[row * 384 + c + j]));
    } else if (t < 144) {
        int c = (t - 96) * 4;
        #pragma unroll
        for (int j = 0; j < 4; j++) v[j] = attn[row * 192 + c + j];
    } else {
        int c = (t - 144) * 4;
        #pragma unroll
        for (int j = 0; j < 4; j++)
            v[j] = __float2half(__half2float(cut[row * 192 + c + j]) *
                                __half2float(xe2[row * 192 + c + j]));
    }
    *(uint2*)(cat + row * 768 + t * 4) = *(uint2*)v;
}

// ---------------- launch ----------------
extern "C" void kernel_launch(void* const* d_in, const int* in_sizes, int n_in,
                              void* d_out, int out_size)
{
    const float* x       = (const float*)d_in[0];
    const float* x_e     = (const float*)d_in[1];
    const float* norm_w  = (const float*)d_in[2];
    const float* norm_b  = (const float*)d_in[3];
    const float* norme_w = (const float*)d_in[4];
    const float* norme_b = (const float*)d_in[5];
    const float* q_w     = (const float*)d_in[6];
    const float* q_b     = (const float*)d_in[7];
    const float* qcut_w  = (const float*)d_in[8];
    const float* qcut_b  = (const float*)d_in[9];
    const float* a_w     = (const float*)d_in[10];
    const float* a_b     = (const float*)d_in[11];
    const float* l_w     = (const float*)d_in[12];
    const float* l_b     = (const float*)d_in[13];
    const float* conv_w  = (const float*)d_in[14];
    const float* conv_b  = (const float*)d_in[15];
    const float* econv_w = (const float*)d_in[16];
    const float* econv_b = (const float*)d_in[17];
    const float* efore_w = (const float*)d_in[18];
    const float* efore_b = (const float*)d_in[19];
    const float* eback_w = (const float*)d_in[20];
    const float* eback_b = (const float*)d_in[21];
    const float* kv_w    = (const float*)d_in[22];
    const float* kv_b    = (const float*)d_in[23];
    const float* scl_w   = (const float*)d_in[24];
    const float* scl_b   = (const float*)d_in[25];
    const float* proj_w  = (const float*)d_in[26];
    const float* proj_b  = (const float*)d_in[27];
    const float* proje_w = (const float*)d_in[28];
    const float* proje_b = (const float*)d_in[29];
    float* out = (float*)d_out;
    float* out_x  = out;
    float* out_xe = out + (size_t)MM * CC;

    __half *xn,*xen,*qb,*cutb,*lx,*clx,*ab,*ef,*efc,*xe2,*attnb,*catb;
    __half *tq,*tl,*ta,*tkv,*tqcut,*tefore,*teback,*tproj,*tproje;
    float *kvb,*mb,*pb,*ob;
    cudaGetSymbolAddress((void**)&xn,   g_xn);
    cudaGetSymbolAddress((void**)&xen,  g_xen);
    cudaGetSymbolAddress((void**)&qb,   g_q);
    cudaGetSymbolAddress((void**)&cutb, g_cut);
    cudaGetSymbolAddress((void**)&lx,   g_lx);
    cudaGetSymbolAddress((void**)&clx,  g_clx);
    cudaGetSymbolAddress((void**)&ab,   g_a);
    cudaGetSymbolAddress((void**)&kvb,  g_kv);
    cudaGetSymbolAddress((void**)&ef,   g_ef);
    cudaGetSymbolAddress((void**)&efc,  g_efc);
    cudaGetSymbolAddress((void**)&xe2,  g_xe2);
    cudaGetSymbolAddress((void**)&mb,   g_m);
    cudaGetSymbolAddress((void**)&pb,   g_p);
    cudaGetSymbolAddress((void**)&ob,   g_o);
    cudaGetSymbolAddress((void**)&attnb,g_attn);
    cudaGetSymbolAddress((void**)&catb, g_cat);
    cudaGetSymbolAddress((void**)&tq,     g_tq);
    cudaGetSymbolAddress((void**)&tl,     g_tl);
    cudaGetSymbolAddress((void**)&ta,     g_ta);
    cudaGetSymbolAddress((void**)&tkv,    g_tkv);
    cudaGetSymbolAddress((void**)&tqcut,  g_tqcut);
    cudaGetSymbolAddress((void**)&tefore, g_tefore);
    cudaGetSymbolAddress((void**)&teback, g_teback);
    cudaGetSymbolAddress((void**)&tproj,  g_tproj);
    cudaGetSymbolAddress((void**)&tproje, g_tproje);

    cudaFuncSetAttribute(h16_gemm_kernel, cudaFuncAttributeMaxDynamicSharedMemorySize, GEMM_SMEM);

    // 0) all weight transposes in one launch
    transpose_all_kernel<<<4992, 256>>>(q_w, l_w, a_w, kv_w, qcut_w, efore_w, eback_w,
                                        proj_w, proje_w,
                                        tq, tl, ta, tkv, tqcut, tefore, teback, tproj, tproje);

    // 1) LayerNorms (warp per row, half out)
    ln_kernel<<<MM / 8, 256>>>(x,   norm_w,  norm_b,  xn,  CC);
    ln_kernel<<<MM / 8, 256>>>(x_e, norme_w, norme_b, xen, C2);

    // 2) pooled shortcut queries -> m (scaled, fp32)
    pool_scl_kernel<<<BB * 49, 192>>>(xn, xen, scl_w, scl_b, mb);

    // 3) q / cut / lx(gelu) GEMMs (fp16 tensor cores)
    dim3 gN384(3, MM / 128), gN192(2, MM / 128);
    h16_gemm_kernel<<<gN384, 256, GEMM_SMEM>>>(xn, tq,    q_b,    nullptr, qb,   384, 384, 0);
    h16_gemm_kernel<<<gN192, 256, GEMM_SMEM>>>(xn, tqcut, qcut_b, nullptr, cutb, 192, 384, 0);
    h16_gemm_kernel<<<gN384, 256, GEMM_SMEM>>>(xn, tl,    l_b,    nullptr, lx,   384, 384, 1);

    // 4) depthwise conv on lx, then a / kv GEMMs (kv -> fp32 for attention)
    dwconv7_kernel<<<dim3(4, 4, BB * (CC / 8)), 196>>>(lx, conv_w, conv_b, clx, CC);
    h16_gemm_kernel<<<gN384, 256, GEMM_SMEM>>>(clx, ta,  a_b,  nullptr, ab, 384, 384, 0);
    h16_gemm_kernel<<<gN384, 256, GEMM_SMEM>>>(lx,  tkv, kv_b, kvb, nullptr, 384, 384, 0);

    // 5) attention + bilinear upsample
    attn_kernel<<<BB * NHD, 256>>>(kvb, mb, pb, ob);
    upsample_kernel<<<dim3(WW, HH, BB), C2>>>(ob, attnb);

    // 6) x_e depthwise branch
    h16_gemm_kernel<<<gN192, 256, GEMM_SMEM>>>(xen, tefore, efore_b, nullptr, ef, 192, 192, 0);
    dwconv7_kernel<<<dim3(4, 4, BB * (C2 / 8)), 196>>>(ef, econv_w, econv_b, efc, C2);
    h16_gemm_kernel<<<gN192, 256, GEMM_SMEM>>>(efc, teback, eback_b, nullptr, xe2, 192, 192, 0);

    // 7) concat + final projections (fp32 out)
    cat_kernel<<<MM, 192>>>(qb, ab, attnb, cutb, xe2, catb);
    h16_gemm_kernel<<<gN384, 256, GEMM_SMEM>>>(catb, tproj,  proj_b,  out_x,  nullptr, 384, 768, 0);
    h16_gemm_kernel<<<gN192, 256, GEMM_SMEM>>>(catb, tproje, proje_b, out_xe, nullptr, 192, 768, 0);
}

// round 7
// speedup vs baseline: 6.0554x; 1.2895x over previous
#include <cuda_runtime.h>
#include <cuda_fp16.h>
#include <math.h>
#include <stdint.h>

// ---------------- problem constants ----------------
#define BB   16
#define HH   56
#define WW   56
#define CC   384
#define C2   192
#define NHD  8
#define HD2  24
#define MM   (BB*HH*WW)        // 50176 tokens
#define HW   (HH*WW)           // 3136
#define KT   112               // attn key tile: 3136 = 28*112
#define SCALE_F 0.20412414523193154f

// ---------------- scratch (device globals; no allocation allowed) ----------------
__device__ __align__(16) __half g_xn  [(size_t)MM*CC];
__device__ __align__(16) __half g_xen [(size_t)MM*C2];
__device__ __align__(16) __half g_q   [(size_t)MM*CC];
__device__ __align__(16) __half g_cut [(size_t)MM*C2];
__device__ __align__(16) __half g_lx  [(size_t)MM*CC];
__device__ __align__(16) __half g_clx [(size_t)MM*CC];
__device__ __align__(16) __half g_a   [(size_t)MM*CC];
__device__ __align__(16) float  g_kv  [(size_t)MM*CC];    // attn input stays fp32
__device__ __align__(16) __half g_ef  [(size_t)MM*C2];
__device__ __align__(16) __half g_efc [(size_t)MM*C2];
__device__ __align__(16) __half g_xe2 [(size_t)MM*C2];
__device__ __align__(16) float  g_m   [(size_t)BB*NHD*49*HD2];
__device__ __align__(16) float  g_o   [(size_t)BB*NHD*49*HD2];
__device__ __align__(16) __half g_cat [(size_t)MM*768];

// transposed (+zero-padded) weights, fp16: Bt[n*K + k] = h(W[k*N + n])
__device__ __align__(16) __half g_tq    [384*384];
__device__ __align__(16) __half g_tl    [384*384];
__device__ __align__(16) __half g_ta    [384*384];
__device__ __align__(16) __half g_tkv   [384*384];
__device__ __align__(16) __half g_tqcut [256*384];
__device__ __align__(16) __half g_tefore[256*192];
__device__ __align__(16) __half g_teback[256*192];
__device__ __align__(16) __half g_tproj [384*768];
__device__ __align__(16) __half g_tproje[256*768];

// ---------------- PTX helpers (sm_80+ features only; no 'a'-gated instrs) ----------------
__device__ __forceinline__ uint32_t smem_u32(const void* p) {
    uint32_t r;
    asm("{ .reg .u64 t; cvta.to.shared.u64 t, %1; cvt.u32.u64 %0, t; }" : "=r"(r) : "l"(p));
    return r;
}
__device__ __forceinline__ void cp_async16(uint32_t dst, const void* src) {
    asm volatile("cp.async.ca.shared.global [%0], [%1], 16;" :: "r"(dst), "l"(src) : "memory");
}
__device__ __forceinline__ void cp_commit() {
    asm volatile("cp.async.commit_group;" ::: "memory");
}
template<int N>
__device__ __forceinline__ void cp_wait() {
    asm volatile("cp.async.wait_group %0;" :: "n"(N) : "memory");
}
__device__ __forceinline__ void ldsm_x4(uint32_t& r0, uint32_t& r1, uint32_t& r2, uint32_t& r3,
                                        uint32_t addr) {
    asm volatile("ldmatrix.sync.aligned.m8n8.x4.shared.b16 {%0,%1,%2,%3}, [%4];"
                 : "=r"(r0), "=r"(r1), "=r"(r2), "=r"(r3) : "r"(addr));
}
__device__ __forceinline__ void mma_f16(float* c, const uint32_t* a, uint32_t b0, uint32_t b1) {
    asm volatile(
        "mma.sync.aligned.m16n8k16.row.col.f32.f16.f16.f32 "
        "{%0,%1,%2,%3}, {%4,%5,%6,%7}, {%8,%9}, {%0,%1,%2,%3};"
        : "+f"(c[0]), "+f"(c[1]), "+f"(c[2]), "+f"(c[3])
        : "r"(a[0]), "r"(a[1]), "r"(a[2]), "r"(a[3]), "r"(b0), "r"(b1));
}

// ---------------- batched weight transpose + pad + fp16 (one launch) ----------------
__global__ void transpose_all_kernel(
    const float* __restrict__ q_w,     const float* __restrict__ l_w,
    const float* __restrict__ a_w,     const float* __restrict__ kv_w,
    const float* __restrict__ qcut_w,  const float* __restrict__ efore_w,
    const float* __restrict__ eback_w, const float* __restrict__ proj_w,
    const float* __restrict__ proje_w,
    __half* __restrict__ tq,     __half* __restrict__ tl,
    __half* __restrict__ ta,     __half* __restrict__ tkv,
    __half* __restrict__ tqcut,  __half* __restrict__ tefore,
    __half* __restrict__ teback, __half* __restrict__ tproj,
    __half* __restrict__ tproje)
{
    int idx = blockIdx.x * 256 + threadIdx.x;   // grid exactly 1277952/256 = 4992
    const float* src; __half* dst; int K, N, off;
    if      (idx <  147456) { src=q_w;     dst=tq;     K=384; N=384; off=idx; }
    else if (idx <  294912) { src=l_w;     dst=tl;     K=384; N=384; off=idx- 147456; }
    else if (idx <  442368) { src=a_w;     dst=ta;     K=384; N=384; off=idx- 294912; }
    else if (idx <  589824) { src=kv_w;    dst=tkv;    K=384; N=384; off=idx- 442368; }
    else if (idx <  688128) { src=qcut_w;  dst=tqcut;  K=384; N=192; off=idx- 589824; }
    else if (idx <  737280) { src=efore_w; dst=tefore; K=192; N=192; off=idx- 688128; }
    else if (idx <  786432) { src=eback_w; dst=teback; K=192; N=192; off=idx- 737280; }
    else if (idx < 1081344) { src=proj_w;  dst=tproj;  K=768; N=384; off=idx- 786432; }
    else                    { src=proje_w; dst=tproje; K=768; N=192; off=idx-1081344; }
    int n = off / K, k = off % K;
    float v = (n < N) ? src[(size_t)k * N + n] : 0.f;
    dst[off] = __float2half(v);
}

// ---------------- fp16 tensor-core GEMM (unchanged from round 6) ----------------
#define SSH 72
#define STAGE_BYTES (128 * SSH * 2 * 2)     // A+B per stage = 36864 B
#define GEMM_SMEM (2 * STAGE_BYTES)         // 73728 B
__global__ __launch_bounds__(256, 2)
void h16_gemm_kernel(const __half* __restrict__ A, const __half* __restrict__ Bt,
                     const float* __restrict__ bias, float* __restrict__ Cf,
                     __half* __restrict__ Ch, int N, int K, int act)
{
    extern __shared__ __half smh[];
    const int tid = threadIdx.x, lane = tid & 31, wid = tid >> 5;
    const int bn = blockIdx.x, bm = blockIdx.y;
    const int warpM = (wid & 3) * 32, warpN = (wid >> 2) * 64;

    const __half* Ab = A  + (size_t)bm * 128 * K;
    const __half* Bb = Bt + (size_t)bn * 128 * K;
    uint32_t sb = smem_u32(smh);
    const int ldrow = tid >> 3;
    const int ldch  = tid & 7;

    float acc[2][8][4];
    #pragma unroll
    for (int i = 0; i < 2; i++)
        #pragma unroll
        for (int j = 0; j < 8; j++)
            #pragma unroll
            for (int t = 0; t < 4; t++) acc[i][j][t] = 0.f;

    const int NC = K >> 6;
    const uint32_t aoff = (uint32_t)((lane & 7) + ((lane >> 3) & 1) * 8) * 144 + (lane >> 4) * 16;
    const uint32_t boff = (uint32_t)((lane & 7) + (lane >> 4) * 8) * 144 + ((lane >> 3) & 1) * 16;

    #pragma unroll
    for (int it = 0; it < 4; it++) {
        int row = ldrow + it * 32;
        uint32_t o = (uint32_t)row * 144 + ldch * 16;
        cp_async16(sb + o, Ab + (size_t)row * K + ldch * 8);
        cp_async16(sb + 128 * SSH * 2 + o, Bb + (size_t)row * K + ldch * 8);
    }
    cp_commit();

    for (int c = 0; c < NC; c++) {
        int buf = c & 1;
        if (c + 1 < NC) {
            uint32_t stage = sb + (uint32_t)((c + 1) & 1) * STAGE_BYTES;
            const __half* ga = Ab + (c + 1) * 64;
            const __half* gb = Bb + (c + 1) * 64;
            #pragma unroll
            for (int it = 0; it < 4; it++) {
                int row = ldrow + it * 32;
                uint32_t o = (uint32_t)row * 144 + ldch * 16;
                cp_async16(stage + o, ga + (size_t)row * K + ldch * 8);
                cp_async16(stage + 128 * SSH * 2 + o, gb + (size_t)row * K + ldch * 8);
            }
            cp_commit();
            cp_wait<1>();
        } else {
            cp_wait<0>();
        }
        __syncthreads();

        uint32_t sA = sb + (uint32_t)buf * STAGE_BYTES + (uint32_t)warpM * 144 + aoff;
        uint32_t sBv = sb + (uint32_t)buf * STAGE_BYTES + 128 * SSH * 2 + (uint32_t)warpN * 144 + boff;

        #pragma unroll
        for (int ks = 0; ks < 4; ks++) {
            uint32_t afr[2][4];
            ldsm_x4(afr[0][0], afr[0][1], afr[0][2], afr[0][3], sA + ks * 32);
            ldsm_x4(afr[1][0], afr[1][1], afr[1][2], afr[1][3], sA + 16 * 144 + ks * 32);
            #pragma unroll
            for (int ntp = 0; ntp < 4; ntp++) {
                uint32_t b0, b1, b2, b3;
                ldsm_x4(b0, b1, b2, b3, sBv + (uint32_t)ntp * 16 * 144 + ks * 32);
                mma_f16(acc[0][ntp * 2],     afr[0], b0, b1);
                mma_f16(acc[1][ntp * 2],     afr[1], b0, b1);
                mma_f16(acc[0][ntp * 2 + 1], afr[0], b2, b3);
                mma_f16(acc[1][ntp * 2 + 1], afr[1], b2, b3);
            }
        }
        __syncthreads();
    }

    #pragma unroll
    for (int mt = 0; mt < 2; mt++) {
        size_t row0 = (size_t)bm * 128 + warpM + mt * 16 + (lane >> 2);
        #pragma unroll
        for (int nt = 0; nt < 8; nt++) {
            int gcol = bn * 128 + warpN + nt * 8 + (lane & 3) * 2;
            if (gcol < N) {
                float bs0 = bias[gcol], bs1 = bias[gcol + 1];
                float v0 = acc[mt][nt][0] + bs0;
                float v1 = acc[mt][nt][1] + bs1;
                float v2 = acc[mt][nt][2] + bs0;
                float v3 = acc[mt][nt][3] + bs1;
                if (act == 1) {
                    v0 = 0.5f*v0*(1.f+erff(v0*0.70710678118654752f));
                    v1 = 0.5f*v1*(1.f+erff(v1*0.70710678118654752f));
                    v2 = 0.5f*v2*(1.f+erff(v2*0.70710678118654752f));
                    v3 = 0.5f*v3*(1.f+erff(v3*0.70710678118654752f));
                }
                if (Ch) {
                    __half2 h0; h0.x = __float2half(v0); h0.y = __float2half(v1);
                    __half2 h1; h1.x = __float2half(v2); h1.y = __float2half(v3);
                    *(__half2*)(Ch + row0 * (size_t)N + gcol) = h0;
                    *(__half2*)(Ch + (row0 + 8) * (size_t)N + gcol) = h1;
                } else {
                    float2 p0; p0.x = v0; p0.y = v1;
                    float2 p1; p1.x = v2; p1.y = v3;
                    *(float2*)(Cf + row0 * (size_t)N + gcol) = p0;
                    *(float2*)(Cf + (row0 + 8) * (size_t)N + gcol) = p1;
                }
            }
        }
    }
}

// ---------------- LayerNorm: one warp per row, fp16 output ----------------
__global__ void ln_kernel(const float* __restrict__ x, const float* __restrict__ w,
                          const float* __restrict__ b, __half* __restrict__ out, int C)
{
    int row = blockIdx.x * 8 + (threadIdx.x >> 5);
    int lane = threadIdx.x & 31;
    const float* xr = x + (size_t)row * C;
    __half* orow = out + (size_t)row * C;

    int n = C >> 5;
    float local[12];
    float s = 0.f;
    for (int i = 0; i < n; i++) { float v = xr[lane + 32 * i]; local[i] = v; s += v; }
    #pragma unroll
    for (int o = 16; o; o >>= 1) s += __shfl_xor_sync(0xffffffffu, s, o);
    float mean = s / (float)C;

    float ss = 0.f;
    for (int i = 0; i < n; i++) { float d = local[i] - mean; ss += d * d; }
    #pragma unroll
    for (int o = 16; o; o >>= 1) ss += __shfl_xor_sync(0xffffffffu, ss, o);
    float rstd = rsqrtf(ss / (float)C + 1e-6f);

    for (int i = 0; i < n; i++) {
        int cidx = lane + 32 * i;
        orow[cidx] = __float2half((local[i] - mean) * rstd * w[cidx] + b[cidx]);
    }
}

// ---------------- pooled shortcut queries + scl GEMM + SCALE fold (half2 loads) ----------------
__global__ void pool_scl_kernel(const __half* __restrict__ xn, const __half* __restrict__ xen,
                                const float* __restrict__ sw, const float* __restrict__ sb,
                                float* __restrict__ mout)
{
    __shared__ float pooled[576];
    int blk = blockIdx.x; int b = blk / 49, qi = blk % 49;
    int py = qi / 7, px = qi % 7;
    int tid = threadIdx.x;    // 192 threads

    for (int ch2 = tid; ch2 < 288; ch2 += 192) {
        float sx = 0.f, sy = 0.f;
        if (ch2 < 192) {
            const __half2* base = (const __half2*)(xn + ((size_t)(b * HH + py * 8) * WW + px * 8) * CC) + ch2;
            #pragma unroll
            for (int hy = 0; hy < 8; hy++)
                #pragma unroll
                for (int wx = 0; wx < 8; wx++) {
                    float2 v = __half22float2(base[(size_t)(hy * WW + wx) * 192]);
                    sx += v.x; sy += v.y;
                }
        } else {
            const __half2* base = (const __half2*)(xen + ((size_t)(b * HH + py * 8) * WW + px * 8) * C2) + (ch2 - 192);
            #pragma unroll
            for (int hy = 0; hy < 8; hy++)
                #pragma unroll
                for (int wx = 0; wx < 8; wx++) {
                    float2 v = __half22float2(base[(size_t)(hy * WW + wx) * 96]);
                    sx += v.x; sy += v.y;
                }
        }
        pooled[ch2 * 2]     = sx * (1.0f / 64.0f);
        pooled[ch2 * 2 + 1] = sy * (1.0f / 64.0f);
    }
    __syncthreads();

    int j = tid;
    float a = sb[j];
    for (int kk = 0; kk < 576; kk++) a += pooled[kk] * sw[(size_t)kk * C2 + j];
    a *= SCALE_F;
    mout[((size_t)(b * NHD + j / HD2) * 49 + qi) * HD2 + (j % HD2)] = a;
}

// ---------------- depthwise 7x7 conv, half in / half out (fp32 math) ----------------
__global__ void dwconv7_kernel(const __half* __restrict__ in, const float* __restrict__ w,
                               const float* __restrict__ bias, __half* __restrict__ out, int C)
{
    __shared__ float s_in[8][400];
    __shared__ float s_w[8][49];
    __shared__ float s_b[8];
    __shared__ __half s_out[196][8];

    int nchunk = C >> 3;
    int b  = blockIdx.z / nchunk;
    int c0 = (blockIdx.z % nchunk) << 3;
    int ty0 = blockIdx.y * 14, tx0 = blockIdx.x * 14;
    int tid = threadIdx.x;   // 196

    for (int idx = tid; idx < 3200; idx += 196) {
        int p = idx >> 3, cc = idx & 7;
        int iy = p / 20, ix = p % 20;
        int gy = ty0 + iy - 3, gx = tx0 + ix - 3;
        float v = 0.f;
        if (gy >= 0 && gy < HH && gx >= 0 && gx < WW)
            v = __half2float(in[(((size_t)b * HH + gy) * WW + gx) * C + c0 + cc]);
        s_in[cc][p] = v;
    }
    for (int idx = tid; idx < 392; idx += 196)
        s_w[idx / 49][idx % 49] = w[(size_t)(c0 + idx / 49) * 49 + idx % 49];
    if (tid < 8) s_b[tid] = bias[c0 + tid];
    __syncthreads();

    int ty = tid / 14, tx = tid % 14;
    float acc[8];
    #pragma unroll
    for (int cc = 0; cc < 8; cc++) acc[cc] = s_b[cc];
    #pragma unroll
    for (int ky = 0; ky < 7; ky++)
        #pragma unroll
        for (int kx = 0; kx < 7; kx++) {
            int p = (ty + ky) * 20 + tx + kx;
            #pragma unroll
            for (int cc = 0; cc < 8; cc++) acc[cc] += s_in[cc][p] * s_w[cc][ky * 7 + kx];
        }
    #pragma unroll
    for (int cc = 0; cc < 8; cc++) s_out[tid][cc] = __float2half(acc[cc]);
    __syncthreads();

    for (int idx = tid; idx < 1568; idx += 196) {
        int p = idx >> 3, cc = idx & 7;
        int oy = ty0 + p / 14, ox = tx0 + p % 14;
        out[(((size_t)b * HH + oy) * WW + ox) * C + c0 + cc] = s_out[p][cc];
    }
}

// ---------------- flash attention: single pass, no global scratch ----------------
// smem float offsets (all row starts 16B-aligned):
#define OM   0          // m 49 x 28 (stride 28, 24 used)
#define OK0  1372
#define OK1  4508
#define OV0  7644
#define OV1  10780
#define OS   13916      // scores 49 x 112   (reused as 1176x4 reduction)
#define OMX  19404
#define OSM  19453
#define OSC  19502
#define ATTN_SMEM (19551 * 4)

__global__ __launch_bounds__(256)
void attn_kernel(const float* __restrict__ kvb, const float* __restrict__ m,
                 float* __restrict__ o)
{
    extern __shared__ float sm[];
    const int bh = blockIdx.x, b = bh >> 3, h = bh & 7;
    const int tid = threadIdx.x, lane = tid & 31, wid = tid >> 5;
    uint32_t sb = smem_u32(sm);

    const float* kbase = kvb + (size_t)b * HW * CC + h * HD2;
    const float* vbase = kbase + C2;

    // init m (stride 28), max/sum
    for (int idx = tid; idx < 1176; idx += 256) {
        int q = idx / 24, d = idx % 24;
        sm[OM + q * 28 + d] = m[(size_t)bh * 1176 + idx];
    }
    if (tid < 49) { sm[OMX + tid] = -1e30f; sm[OSM + tid] = 0.f; }

    // PV thread mapping (persistent accumulators)
    const int pvc = tid & 3, pvg = tid >> 2;          // chunk, group
    const int pq0 = (pvg / 8) * 7, pd0 = (pvg % 8) * 3;
    const bool pv_act = (tid < 224);
    float acc[7][3];
    #pragma unroll
    for (int i = 0; i < 7; i++)
        #pragma unroll
        for (int j = 0; j < 3; j++) acc[i][j] = 0.f;

    // score thread mapping
    const int sqb = tid / 28, skb = tid % 28;
    const int sq0 = sqb * 7;
    const bool sc_act = (tid < 196);

    // prefetch tile 0
    {
        for (int idx = tid; idx < 1344; idx += 256) {
            int mat = idx / 672, r = (idx % 672) / 6, p = idx % 6;
            const float* src = (mat ? vbase : kbase) + (size_t)r * CC + p * 4;
            uint32_t dst = sb + ((mat ? OV0 : OK0) + r * 28 + p * 4) * 4;
            cp_async16(dst, src);
        }
        cp_commit();
    }

    for (int t = 0; t < 28; t++) {
        int buf = t & 1;
        if (t + 1 < 28) {
            int kt1 = (t + 1) * KT;
            int nb = buf ^ 1;
            for (int idx = tid; idx < 1344; idx += 256) {
                int mat = idx / 672, r = (idx % 672) / 6, p = idx % 6;
                const float* src = (mat ? vbase : kbase) + (size_t)(kt1 + r) * CC + p * 4;
                uint32_t dst = sb + ((mat ? (nb ? OV1 : OV0) : (nb ? OK1 : OK0)) + r * 28 + p * 4) * 4;
                cp_async16(dst, src);
            }
            cp_commit();
            cp_wait<1>();
        } else {
            cp_wait<0>();
        }
        __syncthreads();                              // (B) tile t k/v + init visible

        // ---- scores: 7q x 4k per thread, float4 fragments ----
        if (sc_act) {
            const float4* k4 = (const float4*)(sm + (buf ? OK1 : OK0));
            const float4* m4 = (const float4*)(sm + OM);
            float sc[7][4];
            #pragma unroll
            for (int i = 0; i < 7; i++)
                #pragma unroll
                for (int j = 0; j < 4; j++) sc[i][j] = 0.f;
            #pragma unroll
            for (int d4 = 0; d4 < 6; d4++) {
                float4 kv4[4], mm4[7];
                #pragma unroll
                for (int j = 0; j < 4; j++) kv4[j] = k4[(skb + 28 * j) * 7 + d4];
                #pragma unroll
                for (int i = 0; i < 7; i++) mm4[i] = m4[(sq0 + i) * 7 + d4];
                #pragma unroll
                for (int i = 0; i < 7; i++)
                    #pragma unroll
                    for (int j = 0; j < 4; j++)
                        sc[i][j] += mm4[i].x * kv4[j].x + mm4[i].y * kv4[j].y
                                  + mm4[i].z * kv4[j].z + mm4[i].w * kv4[j].w;
            }
            #pragma unroll
            for (int i = 0; i < 7; i++)
                #pragma unroll
                for (int j = 0; j < 4; j++)
                    sm[OS + (sq0 + i) * 112 + skb + 28 * j] = sc[i][j];
        }
        __syncthreads();                              // (C) scores visible

        // ---- per-row max / exp / sum (warp per row) ----
        for (int q = wid; q < 49; q += 8) {
            float* row = sm + OS + q * 112;
            float v0 = row[lane], v1 = row[lane + 32], v2 = row[lane + 64];
            float v3 = (lane < 16) ? row[lane + 96] : -1e30f;
            float tmax = fmaxf(fmaxf(v0, v1), fmaxf(v2, v3));
            #pragma unroll
            for (int off = 16; off; off >>= 1)
                tmax = fmaxf(tmax, __shfl_xor_sync(0xffffffffu, tmax, off));
            float mold = sm[OMX + q];
            float mnew = fmaxf(mold, tmax);
            float e0 = expf(v0 - mnew), e1 = expf(v1 - mnew), e2 = expf(v2 - mnew);
            float e3 = (lane < 16) ? expf(v3 - mnew) : 0.f;
            row[lane] = e0; row[lane + 32] = e1; row[lane + 64] = e2;
            if (lane < 16) row[lane + 96] = e3;
            float tsum = e0 + e1 + e2 + e3;
            #pragma unroll
            for (int off = 16; off; off >>= 1)
                tsum += __shfl_xor_sync(0xffffffffu, tsum, off);
            if (lane == 0) {
                float scale = expf(mold - mnew);
                sm[OSC + q] = scale;
                sm[OSM + q] = sm[OSM + q] * scale + tsum;
                sm[OMX + q] = mnew;
            }
        }
        __syncthreads();                              // (D) exp'd scores + scale visible

        // ---- PV: rescale + accumulate (7q x 3d x 28 keys of own chunk) ----
        if (pv_act) {
            #pragma unroll
            for (int i = 0; i < 7; i++) {
                float scl = sm[OSC + pq0 + i];
                #pragma unroll
                for (int j = 0; j < 3; j++) acc[i][j] *= scl;
            }
            const float* vb = sm + (buf ? OV1 : OV0);
            for (int lk = 0; lk < 28; lk++) {
                int kk = pvc * 28 + lk;
                float vv0 = vb[kk * 28 + pd0];
                float vv1 = vb[kk * 28 + pd0 + 1];
                float vv2 = vb[kk * 28 + pd0 + 2];
                #pragma unroll
                for (int i = 0; i < 7; i++) {
                    float pp = sm[OS + (pq0 + i) * 112 + kk];
                    acc[i][0] += pp * vv0;
                    acc[i][1] += pp * vv1;
                    acc[i][2] += pp * vv2;
                }
            }
        }
        __syncthreads();                              // (E) PV done; safe to refill buf^1
    }

    // ---- merge 4 chunk partials + normalize (reuse score smem) ----
    if (pv_act) {
        #pragma unroll
        for (int i = 0; i < 7; i++)
            #pragma unroll
            for (int j = 0; j < 3; j++)
                sm[OS + ((pq0 + i) * 24 + pd0 + j) * 4 + pvc] = acc[i][j];
    }
    __syncthreads();
    for (int idx = tid; idx < 1176; idx += 256) {
        int q = idx / 24;
        float r = sm[OS + idx * 4] + sm[OS + idx * 4 + 1]
                + sm[OS + idx * 4 + 2] + sm[OS + idx * 4 + 3];
        o[(size_t)bh * 1176 + idx] = r / sm[OSM + q];
    }
}

// ---------------- concat [q*a | bilinear(o) | cut*xe2], fused upsample ----------------
__global__ void cat_kernel(const __half* __restrict__ q, const __half* __restrict__ a,
                           const float* __restrict__ o, const __half* __restrict__ cut,
                           const __half* __restrict__ xe2, __half* __restrict__ cat)
{
    size_t row = blockIdx.x;
    int t = threadIdx.x;                 // 192 threads, 4 halves each
    __half v[4];
    if (t < 96) {
        int c = t * 4;
        #pragma unroll
        for (int j = 0; j < 4; j++)
            v[j] = __float2half(__half2float(q[row * 384 + c + j]) *
                                __half2float(a[row * 384 + c + j]));
    } else if (t < 144) {
        int c = (t - 96) * 4;
        int b = (int)(row / HW); int rem = (int)(row % HW);
        int y = rem / WW, x = rem % WW;
        int h = c / HD2, d = c % HD2;
        float fy = (y + 0.5f) * 0.125f - 0.5f;
        float fx = (x + 0.5f) * 0.125f - 0.5f;
        int y0 = (int)floorf(fy); float ty = fy - (float)y0;
        int x0 = (int)floorf(fx); float tx = fx - (float)x0;
        int y0c = max(y0, 0), y1c = min(y0 + 1, 6);
        int x0c = max(x0, 0), x1c = min(x0 + 1, 6);
        const float* ob = o + ((size_t)(b * NHD + h) * 49) * HD2 + d;
        float4 v00 = *(const float4*)(ob + (y0c * 7 + x0c) * HD2);
        float4 v01 = *(const float4*)(ob + (y0c * 7 + x1c) * HD2);
        float4 v10 = *(const float4*)(ob + (y1c * 7 + x0c) * HD2);
        float4 v11 = *(const float4*)(ob + (y1c * 7 + x1c) * HD2);
        float w00 = (1.f - ty) * (1.f - tx), w01 = (1.f - ty) * tx;
        float w10 = ty * (1.f - tx), w11 = ty * tx;
        v[0] = __float2half(w00 * v00.x + w01 * v01.x + w10 * v10.x + w11 * v11.x);
        v[1] = __float2half(w00 * v00.y + w01 * v01.y + w10 * v10.y + w11 * v11.y);
        v[2] = __float2half(w00 * v00.z + w01 * v01.z + w10 * v10.z + w11 * v11.z);
        v[3] = __float2half(w00 * v00.w + w01 * v01.w + w10 * v10.w + w11 * v11.w);
    } else {
        int c = (t - 144) * 4;
        #pragma unroll
        for (int j = 0; j < 4; j++)
            v[j] = __float2half(__half2float(cut[row * 192 + c + j]) *
                                __half2float(xe2[row * 192 + c + j]));
    }
    *(uint2*)(cat + row * 768 + t * 4) = *(uint2*)v;
}

// ---------------- launch ----------------
extern "C" void kernel_launch(void* const* d_in, const int* in_sizes, int n_in,
                              void* d_out, int out_size)
{
    const float* x       = (const float*)d_in[0];
    const float* x_e     = (const float*)d_in[1];
    const float* norm_w  = (const float*)d_in[2];
    const float* norm_b  = (const float*)d_in[3];
    const float* norme_w = (const float*)d_in[4];
    const float* norme_b = (const float*)d_in[5];
    const float* q_w     = (const float*)d_in[6];
    const float* q_b     = (const float*)d_in[7];
    const float* qcut_w  = (const float*)d_in[8];
    const float* qcut_b  = (const float*)d_in[9];
    const float* a_w     = (const float*)d_in[10];
    const float* a_b     = (const float*)d_in[11];
    const float* l_w     = (const float*)d_in[12];
    const float* l_b     = (const float*)d_in[13];
    const float* conv_w  = (const float*)d_in[14];
    const float* conv_b  = (const float*)d_in[15];
    const float* econv_w = (const float*)d_in[16];
    const float* econv_b = (const float*)d_in[17];
    const float* efore_w = (const float*)d_in[18];
    const float* efore_b = (const float*)d_in[19];
    const float* eback_w = (const float*)d_in[20];
    const float* eback_b = (const float*)d_in[21];
    const float* kv_w    = (const float*)d_in[22];
    const float* kv_b    = (const float*)d_in[23];
    const float* scl_w   = (const float*)d_in[24];
    const float* scl_b   = (const float*)d_in[25];
    const float* proj_w  = (const float*)d_in[26];
    const float* proj_b  = (const float*)d_in[27];
    const float* proje_w = (const float*)d_in[28];
    const float* proje_b = (const float*)d_in[29];
    float* out = (float*)d_out;
    float* out_x  = out;
    float* out_xe = out + (size_t)MM * CC;

    __half *xn,*xen,*qb,*cutb,*lx,*clx,*ab,*ef,*efc,*xe2,*catb;
    __half *tq,*tl,*ta,*tkv,*tqcut,*tefore,*teback,*tproj,*tproje;
    float *kvb,*mb,*ob;
    cudaGetSymbolAddress((void**)&xn,   g_xn);
    cudaGetSymbolAddress((void**)&xen,  g_xen);
    cudaGetSymbolAddress((void**)&qb,   g_q);
    cudaGetSymbolAddress((void**)&cutb, g_cut);
    cudaGetSymbolAddress((void**)&lx,   g_lx);
    cudaGetSymbolAddress((void**)&clx,  g_clx);
    cudaGetSymbolAddress((void**)&ab,   g_a);
    cudaGetSymbolAddress((void**)&kvb,  g_kv);
    cudaGetSymbolAddress((void**)&ef,   g_ef);
    cudaGetSymbolAddress((void**)&efc,  g_efc);
    cudaGetSymbolAddress((void**)&xe2,  g_xe2);
    cudaGetSymbolAddress((void**)&mb,   g_m);
    cudaGetSymbolAddress((void**)&ob,   g_o);
    cudaGetSymbolAddress((void**)&catb, g_cat);
    cudaGetSymbolAddress((void**)&tq,     g_tq);
    cudaGetSymbolAddress((void**)&tl,     g_tl);
    cudaGetSymbolAddress((void**)&ta,     g_ta);
    cudaGetSymbolAddress((void**)&tkv,    g_tkv);
    cudaGetSymbolAddress((void**)&tqcut,  g_tqcut);
    cudaGetSymbolAddress((void**)&tefore, g_tefore);
    cudaGetSymbolAddress((void**)&teback, g_teback);
    cudaGetSymbolAddress((void**)&tproj,  g_tproj);
    cudaGetSymbolAddress((void**)&tproje, g_tproje);

    cudaFuncSetAttribute(h16_gemm_kernel, cudaFuncAttributeMaxDynamicSharedMemorySize, GEMM_SMEM);
    cudaFuncSetAttribute(attn_kernel, cudaFuncAttributeMaxDynamicSharedMemorySize, ATTN_SMEM);

    // 0) all weight transposes in one launch
    transpose_all_kernel<<<4992, 256>>>(q_w, l_w, a_w, kv_w, qcut_w, efore_w, eback_w,
                                        proj_w, proje_w,
                                        tq, tl, ta, tkv, tqcut, tefore, teback, tproj, tproje);

    // 1) LayerNorms (warp per row, half out)
    ln_kernel<<<MM / 8, 256>>>(x,   norm_w,  norm_b,  xn,  CC);
    ln_kernel<<<MM / 8, 256>>>(x_e, norme_w, norme_b, xen, C2);

    // 2) pooled shortcut queries -> m (scaled, fp32)
    pool_scl_kernel<<<BB * 49, 192>>>(xn, xen, scl_w, scl_b, mb);

    // 3) q / cut / lx(gelu) GEMMs (fp16 tensor cores)
    dim3 gN384(3, MM / 128), gN192(2, MM / 128);
    h16_gemm_kernel<<<gN384, 256, GEMM_SMEM>>>(xn, tq,    q_b,    nullptr, qb,   384, 384, 0);
    h16_gemm_kernel<<<gN192, 256, GEMM_SMEM>>>(xn, tqcut, qcut_b, nullptr, cutb, 192, 384, 0);
    h16_gemm_kernel<<<gN384, 256, GEMM_SMEM>>>(xn, tl,    l_b,    nullptr, lx,   384, 384, 1);

    // 4) depthwise conv on lx, then a / kv GEMMs (kv -> fp32 for attention)
    dwconv7_kernel<<<dim3(4, 4, BB * (CC / 8)), 196>>>(lx, conv_w, conv_b, clx, CC);
    h16_gemm_kernel<<<gN384, 256, GEMM_SMEM>>>(clx, ta,  a_b,  nullptr, ab, 384, 384, 0);
    h16_gemm_kernel<<<gN384, 256, GEMM_SMEM>>>(lx,  tkv, kv_b, kvb, nullptr, 384, 384, 0);

    // 5) flash attention (single pass, no scratch)
    attn_kernel<<<BB * NHD, 256, ATTN_SMEM>>>(kvb, mb, ob);

    // 6) x_e depthwise branch
    h16_gemm_kernel<<<gN192, 256, GEMM_SMEM>>>(xen, tefore, efore_b, nullptr, ef, 192, 192, 0);
    dwconv7_kernel<<<dim3(4, 4, BB * (C2 / 8)), 196>>>(ef, econv_w, econv_b, efc, C2);
    h16_gemm_kernel<<<gN192, 256, GEMM_SMEM>>>(efc, teback, eback_b, nullptr, xe2, 192, 192, 0);

    // 7) concat (fused bilinear upsample) + final projections (fp32 out)
    cat_kernel<<<MM, 192>>>(qb, ab, ob, cutb, xe2, catb);
    h16_gemm_kernel<<<gN384, 256, GEMM_SMEM>>>(catb, tproj,  proj_b,  out_x,  nullptr, 384, 768, 0);
    h16_gemm_kernel<<<gN192, 256, GEMM_SMEM>>>(catb, tproje, proje_b, out_xe, nullptr, 192, 768, 0);
}

// round 8
// speedup vs baseline: 8.9645x; 1.4804x over previous
#include <cuda_runtime.h>
#include <cuda_fp16.h>
#include <math.h>
#include <stdint.h>

// ---------------- problem constants ----------------
#define BB   16
#define HH   56
#define WW   56
#define CC   384
#define C2   192
#define NHD  8
#define HD2  24
#define MM   (BB*HH*WW)        // 50176 tokens
#define HW   (HH*WW)           // 3136
#define KT   112               // attn key tile: 3136 = 28*112
#define NSPLIT 4               // attention kv splits (7 tiles each)
#define SCALE_F 0.20412414523193154f

// ---------------- scratch (device globals; no allocation allowed) ----------------
__device__ __align__(16) __half g_xn  [(size_t)MM*CC];
__device__ __align__(16) __half g_xen [(size_t)MM*C2];
__device__ __align__(16) __half g_q   [(size_t)MM*CC];
__device__ __align__(16) __half g_cut [(size_t)MM*C2];
__device__ __align__(16) __half g_lx  [(size_t)MM*CC];
__device__ __align__(16) __half g_clx [(size_t)MM*CC];
__device__ __align__(16) __half g_a   [(size_t)MM*CC];
__device__ __align__(16) float  g_kv  [(size_t)MM*CC];    // attn input stays fp32
__device__ __align__(16) __half g_ef  [(size_t)MM*C2];
__device__ __align__(16) __half g_efc [(size_t)MM*C2];
__device__ __align__(16) __half g_xe2 [(size_t)MM*C2];
__device__ __align__(16) float  g_m   [(size_t)BB*NHD*49*HD2];
__device__ __align__(16) float  g_o   [(size_t)BB*NHD*49*HD2];
__device__ __align__(16) float  g_op  [(size_t)BB*NHD*NSPLIT*49*HD2];  // split partials
__device__ __align__(16) float  g_mx  [(size_t)BB*NHD*NSPLIT*49];
__device__ __align__(16) float  g_sm2 [(size_t)BB*NHD*NSPLIT*49];
__device__ __align__(16) __half g_cat [(size_t)MM*768];

// transposed (+zero-padded) weights, fp16: Bt[n*K + k] = h(W[k*N + n])
__device__ __align__(16) __half g_tq    [384*384];
__device__ __align__(16) __half g_tl    [384*384];
__device__ __align__(16) __half g_ta    [384*384];
__device__ __align__(16) __half g_tkv   [384*384];
__device__ __align__(16) __half g_tqcut [256*384];
__device__ __align__(16) __half g_tefore[256*192];
__device__ __align__(16) __half g_teback[256*192];
__device__ __align__(16) __half g_tproj [384*768];
__device__ __align__(16) __half g_tproje[256*768];

// ---------------- PTX helpers (sm_80+ features only; no 'a'-gated instrs) ----------------
__device__ __forceinline__ uint32_t smem_u32(const void* p) {
    uint32_t r;
    asm("{ .reg .u64 t; cvta.to.shared.u64 t, %1; cvt.u32.u64 %0, t; }" : "=r"(r) : "l"(p));
    return r;
}
__device__ __forceinline__ void cp_async16(uint32_t dst, const void* src) {
    asm volatile("cp.async.ca.shared.global [%0], [%1], 16;" :: "r"(dst), "l"(src) : "memory");
}
__device__ __forceinline__ void cp_commit() {
    asm volatile("cp.async.commit_group;" ::: "memory");
}
template<int N>
__device__ __forceinline__ void cp_wait() {
    asm volatile("cp.async.wait_group %0;" :: "n"(N) : "memory");
}
__device__ __forceinline__ void ldsm_x4(uint32_t& r0, uint32_t& r1, uint32_t& r2, uint32_t& r3,
                                        uint32_t addr) {
    asm volatile("ldmatrix.sync.aligned.m8n8.x4.shared.b16 {%0,%1,%2,%3}, [%4];"
                 : "=r"(r0), "=r"(r1), "=r"(r2), "=r"(r3) : "r"(addr));
}
__device__ __forceinline__ void mma_f16(float* c, const uint32_t* a, uint32_t b0, uint32_t b1) {
    asm volatile(
        "mma.sync.aligned.m16n8k16.row.col.f32.f16.f16.f32 "
        "{%0,%1,%2,%3}, {%4,%5,%6,%7}, {%8,%9}, {%0,%1,%2,%3};"
        : "+f"(c[0]), "+f"(c[1]), "+f"(c[2]), "+f"(c[3])
        : "r"(a[0]), "r"(a[1]), "r"(a[2]), "r"(a[3]), "r"(b0), "r"(b1));
}

// ---------------- batched weight transpose + pad + fp16 (one launch) ----------------
__global__ void transpose_all_kernel(
    const float* __restrict__ q_w,     const float* __restrict__ l_w,
    const float* __restrict__ a_w,     const float* __restrict__ kv_w,
    const float* __restrict__ qcut_w,  const float* __restrict__ efore_w,
    const float* __restrict__ eback_w, const float* __restrict__ proj_w,
    const float* __restrict__ proje_w,
    __half* __restrict__ tq,     __half* __restrict__ tl,
    __half* __restrict__ ta,     __half* __restrict__ tkv,
    __half* __restrict__ tqcut,  __half* __restrict__ tefore,
    __half* __restrict__ teback, __half* __restrict__ tproj,
    __half* __restrict__ tproje)
{
    int idx = blockIdx.x * 256 + threadIdx.x;   // grid exactly 1277952/256 = 4992
    const float* src; __half* dst; int K, N, off;
    if      (idx <  147456) { src=q_w;     dst=tq;     K=384; N=384; off=idx; }
    else if (idx <  294912) { src=l_w;     dst=tl;     K=384; N=384; off=idx- 147456; }
    else if (idx <  442368) { src=a_w;     dst=ta;     K=384; N=384; off=idx- 294912; }
    else if (idx <  589824) { src=kv_w;    dst=tkv;    K=384; N=384; off=idx- 442368; }
    else if (idx <  688128) { src=qcut_w;  dst=tqcut;  K=384; N=192; off=idx- 589824; }
    else if (idx <  737280) { src=efore_w; dst=tefore; K=192; N=192; off=idx- 688128; }
    else if (idx <  786432) { src=eback_w; dst=teback; K=192; N=192; off=idx- 737280; }
    else if (idx < 1081344) { src=proj_w;  dst=tproj;  K=768; N=384; off=idx- 786432; }
    else                    { src=proje_w; dst=tproje; K=768; N=192; off=idx-1081344; }
    int n = off / K, k = off % K;
    float v = (n < N) ? src[(size_t)k * N + n] : 0.f;
    dst[off] = __float2half(v);
}

// ---------------- fp16 tensor-core GEMM (unchanged) ----------------
#define SSH 72
#define STAGE_BYTES (128 * SSH * 2 * 2)     // A+B per stage = 36864 B
#define GEMM_SMEM (2 * STAGE_BYTES)         // 73728 B
__global__ __launch_bounds__(256, 2)
void h16_gemm_kernel(const __half* __restrict__ A, const __half* __restrict__ Bt,
                     const float* __restrict__ bias, float* __restrict__ Cf,
                     __half* __restrict__ Ch, int N, int K, int act)
{
    extern __shared__ __half smh[];
    const int tid = threadIdx.x, lane = tid & 31, wid = tid >> 5;
    const int bn = blockIdx.x, bm = blockIdx.y;
    const int warpM = (wid & 3) * 32, warpN = (wid >> 2) * 64;

    const __half* Ab = A  + (size_t)bm * 128 * K;
    const __half* Bb = Bt + (size_t)bn * 128 * K;
    uint32_t sb = smem_u32(smh);
    const int ldrow = tid >> 3;
    const int ldch  = tid & 7;

    float acc[2][8][4];
    #pragma unroll
    for (int i = 0; i < 2; i++)
        #pragma unroll
        for (int j = 0; j < 8; j++)
            #pragma unroll
            for (int t = 0; t < 4; t++) acc[i][j][t] = 0.f;

    const int NC = K >> 6;
    const uint32_t aoff = (uint32_t)((lane & 7) + ((lane >> 3) & 1) * 8) * 144 + (lane >> 4) * 16;
    const uint32_t boff = (uint32_t)((lane & 7) + (lane >> 4) * 8) * 144 + ((lane >> 3) & 1) * 16;

    #pragma unroll
    for (int it = 0; it < 4; it++) {
        int row = ldrow + it * 32;
        uint32_t o = (uint32_t)row * 144 + ldch * 16;
        cp_async16(sb + o, Ab + (size_t)row * K + ldch * 8);
        cp_async16(sb + 128 * SSH * 2 + o, Bb + (size_t)row * K + ldch * 8);
    }
    cp_commit();

    for (int c = 0; c < NC; c++) {
        int buf = c & 1;
        if (c + 1 < NC) {
            uint32_t stage = sb + (uint32_t)((c + 1) & 1) * STAGE_BYTES;
            const __half* ga = Ab + (c + 1) * 64;
            const __half* gb = Bb + (c + 1) * 64;
            #pragma unroll
            for (int it = 0; it < 4; it++) {
                int row = ldrow + it * 32;
                uint32_t o = (uint32_t)row * 144 + ldch * 16;
                cp_async16(stage + o, ga + (size_t)row * K + ldch * 8);
                cp_async16(stage + 128 * SSH * 2 + o, gb + (size_t)row * K + ldch * 8);
            }
            cp_commit();
            cp_wait<1>();
        } else {
            cp_wait<0>();
        }
        __syncthreads();

        uint32_t sA = sb + (uint32_t)buf * STAGE_BYTES + (uint32_t)warpM * 144 + aoff;
        uint32_t sBv = sb + (uint32_t)buf * STAGE_BYTES + 128 * SSH * 2 + (uint32_t)warpN * 144 + boff;

        #pragma unroll
        for (int ks = 0; ks < 4; ks++) {
            uint32_t afr[2][4];
            ldsm_x4(afr[0][0], afr[0][1], afr[0][2], afr[0][3], sA + ks * 32);
            ldsm_x4(afr[1][0], afr[1][1], afr[1][2], afr[1][3], sA + 16 * 144 + ks * 32);
            #pragma unroll
            for (int ntp = 0; ntp < 4; ntp++) {
                uint32_t b0, b1, b2, b3;
                ldsm_x4(b0, b1, b2, b3, sBv + (uint32_t)ntp * 16 * 144 + ks * 32);
                mma_f16(acc[0][ntp * 2],     afr[0], b0, b1);
                mma_f16(acc[1][ntp * 2],     afr[1], b0, b1);
                mma_f16(acc[0][ntp * 2 + 1], afr[0], b2, b3);
                mma_f16(acc[1][ntp * 2 + 1], afr[1], b2, b3);
            }
        }
        __syncthreads();
    }

    #pragma unroll
    for (int mt = 0; mt < 2; mt++) {
        size_t row0 = (size_t)bm * 128 + warpM + mt * 16 + (lane >> 2);
        #pragma unroll
        for (int nt = 0; nt < 8; nt++) {
            int gcol = bn * 128 + warpN + nt * 8 + (lane & 3) * 2;
            if (gcol < N) {
                float bs0 = bias[gcol], bs1 = bias[gcol + 1];
                float v0 = acc[mt][nt][0] + bs0;
                float v1 = acc[mt][nt][1] + bs1;
                float v2 = acc[mt][nt][2] + bs0;
                float v3 = acc[mt][nt][3] + bs1;
                if (act == 1) {
                    v0 = 0.5f*v0*(1.f+erff(v0*0.70710678118654752f));
                    v1 = 0.5f*v1*(1.f+erff(v1*0.70710678118654752f));
                    v2 = 0.5f*v2*(1.f+erff(v2*0.70710678118654752f));
                    v3 = 0.5f*v3*(1.f+erff(v3*0.70710678118654752f));
                }
                if (Ch) {
                    __half2 h0; h0.x = __float2half(v0); h0.y = __float2half(v1);
                    __half2 h1; h1.x = __float2half(v2); h1.y = __float2half(v3);
                    *(__half2*)(Ch + row0 * (size_t)N + gcol) = h0;
                    *(__half2*)(Ch + (row0 + 8) * (size_t)N + gcol) = h1;
                } else {
                    float2 p0; p0.x = v0; p0.y = v1;
                    float2 p1; p1.x = v2; p1.y = v3;
                    *(float2*)(Cf + row0 * (size_t)N + gcol) = p0;
                    *(float2*)(Cf + (row0 + 8) * (size_t)N + gcol) = p1;
                }
            }
        }
    }
}

// ---------------- LayerNorm: one warp per row, fp16 output ----------------
__global__ void ln_kernel(const float* __restrict__ x, const float* __restrict__ w,
                          const float* __restrict__ b, __half* __restrict__ out, int C)
{
    int row = blockIdx.x * 8 + (threadIdx.x >> 5);
    int lane = threadIdx.x & 31;
    const float* xr = x + (size_t)row * C;
    __half* orow = out + (size_t)row * C;

    int n = C >> 5;
    float local[12];
    float s = 0.f;
    for (int i = 0; i < n; i++) { float v = xr[lane + 32 * i]; local[i] = v; s += v; }
    #pragma unroll
    for (int o = 16; o; o >>= 1) s += __shfl_xor_sync(0xffffffffu, s, o);
    float mean = s / (float)C;

    float ss = 0.f;
    for (int i = 0; i < n; i++) { float d = local[i] - mean; ss += d * d; }
    #pragma unroll
    for (int o = 16; o; o >>= 1) ss += __shfl_xor_sync(0xffffffffu, ss, o);
    float rstd = rsqrtf(ss / (float)C + 1e-6f);

    for (int i = 0; i < n; i++) {
        int cidx = lane + 32 * i;
        orow[cidx] = __float2half((local[i] - mean) * rstd * w[cidx] + b[cidx]);
    }
}

// ---------------- pooled shortcut queries + scl GEMM + SCALE fold (half2 loads) ----------------
__global__ void pool_scl_kernel(const __half* __restrict__ xn, const __half* __restrict__ xen,
                                const float* __restrict__ sw, const float* __restrict__ sb,
                                float* __restrict__ mout)
{
    __shared__ float pooled[576];
    int blk = blockIdx.x; int b = blk / 49, qi = blk % 49;
    int py = qi / 7, px = qi % 7;
    int tid = threadIdx.x;    // 192 threads

    for (int ch2 = tid; ch2 < 288; ch2 += 192) {
        float sx = 0.f, sy = 0.f;
        if (ch2 < 192) {
            const __half2* base = (const __half2*)(xn + ((size_t)(b * HH + py * 8) * WW + px * 8) * CC) + ch2;
            #pragma unroll
            for (int hy = 0; hy < 8; hy++)
                #pragma unroll
                for (int wx = 0; wx < 8; wx++) {
                    float2 v = __half22float2(base[(size_t)(hy * WW + wx) * 192]);
                    sx += v.x; sy += v.y;
                }
        } else {
            const __half2* base = (const __half2*)(xen + ((size_t)(b * HH + py * 8) * WW + px * 8) * C2) + (ch2 - 192);
            #pragma unroll
            for (int hy = 0; hy < 8; hy++)
                #pragma unroll
                for (int wx = 0; wx < 8; wx++) {
                    float2 v = __half22float2(base[(size_t)(hy * WW + wx) * 96]);
                    sx += v.x; sy += v.y;
                }
        }
        pooled[ch2 * 2]     = sx * (1.0f / 64.0f);
        pooled[ch2 * 2 + 1] = sy * (1.0f / 64.0f);
    }
    __syncthreads();

    int j = tid;
    float a = sb[j];
    for (int kk = 0; kk < 576; kk++) a += pooled[kk] * sw[(size_t)kk * C2 + j];
    a *= SCALE_F;
    mout[((size_t)(b * NHD + j / HD2) * 49 + qi) * HD2 + (j % HD2)] = a;
}

// ---------------- depthwise 7x7 conv: register sliding window, FMA-bound ----------------
// block = 14x14 pixel tile x 16 channels, 224 threads, thread = (out row, channel).
// smem pixel-major: s_in[row][x*16+cc], row stride 336 (== 16 mod 32: warp's two
// rows hit disjoint bank halves). 0.28 LDS/FMA vs 2.0 before.
__global__ __launch_bounds__(224)
void dwconv7_kernel(const __half* __restrict__ in, const float* __restrict__ w,
                    const float* __restrict__ bias, __half* __restrict__ out, int C)
{
    __shared__ float s_in[20][336];
    __shared__ float s_w[16][49];
    __shared__ float s_b[16];
    __shared__ __align__(16) __half s_out[196][16];

    int nchunk = C >> 4;
    int b  = blockIdx.z / nchunk;
    int c0 = (blockIdx.z % nchunk) << 4;
    int ty0 = blockIdx.y * 14, tx0 = blockIdx.x * 14;
    int tid = threadIdx.x;   // 224

    // halo load: 20x20 pixels x 16 ch = 800 16B-chunks (8 halves each)
    for (int idx = tid; idx < 800; idx += 224) {
        int p = idx >> 1, h8 = idx & 1;
        int iy = p / 20, ix = p % 20;
        int gy = ty0 + iy - 3, gx = tx0 + ix - 3;
        __half hb[8];
        uint4 z; z.x = z.y = z.z = z.w = 0u;
        *(uint4*)hb = z;
        if (gy >= 0 && gy < HH && gx >= 0 && gx < WW)
            *(uint4*)hb = *(const uint4*)(in + (((size_t)b * HH + gy) * WW + gx) * C + c0 + h8 * 8);
        #pragma unroll
        for (int j = 0; j < 8; j++)
            s_in[iy][ix * 16 + h8 * 8 + j] = __half2float(hb[j]);
    }
    for (int idx = tid; idx < 784; idx += 224)
        s_w[idx / 49][idx % 49] = w[(size_t)(c0 + idx / 49) * 49 + idx % 49];
    if (tid < 16) s_b[tid] = bias[c0 + tid];
    __syncthreads();

    int r = tid >> 4, cc = tid & 15;
    float acc[14];
    #pragma unroll
    for (int x = 0; x < 14; x++) acc[x] = s_b[cc];
    #pragma unroll
    for (int ky = 0; ky < 7; ky++) {
        float wk[7];
        #pragma unroll
        for (int kx = 0; kx < 7; kx++) wk[kx] = s_w[cc][ky * 7 + kx];
        float v[20];
        #pragma unroll
        for (int ix = 0; ix < 20; ix++) v[ix] = s_in[r + ky][ix * 16 + cc];
        #pragma unroll
        for (int kx = 0; kx < 7; kx++)
            #pragma unroll
            for (int x = 0; x < 14; x++) acc[x] += wk[kx] * v[x + kx];
    }
    #pragma unroll
    for (int x = 0; x < 14; x++) s_out[r * 14 + x][cc] = __float2half(acc[x]);
    __syncthreads();

    for (int idx = tid; idx < 392; idx += 224) {
        int p = idx >> 1, h8 = idx & 1;
        int oy = ty0 + p / 14, ox = tx0 + p % 14;
        *(uint4*)(out + (((size_t)b * HH + oy) * WW + ox) * C + c0 + h8 * 8) =
            *(uint4*)&s_out[p][h8 * 8];
    }
}

// ---------------- flash attention, split-K x4 (7 key tiles per CTA) ----------------
#define OM   0          // m 49 x 28 (stride 28, 24 used)
#define OK0  1372
#define OK1  4508
#define OV0  7644
#define OV1  10780
#define OS   13916      // scores 49 x 112   (reused as 1176x4 reduction)
#define OMX  19404
#define OSM  19453
#define OSC  19502
#define ATTN_SMEM (19551 * 4)

__global__ __launch_bounds__(256)
void attn_kernel(const float* __restrict__ kvb, const float* __restrict__ m,
                 float* __restrict__ op, float* __restrict__ mxg, float* __restrict__ smg)
{
    extern __shared__ float sm[];
    const int split = blockIdx.x & (NSPLIT - 1);
    const int bh = blockIdx.x >> 2, b = bh >> 3, h = bh & 7;
    const int tid = threadIdx.x, lane = tid & 31, wid = tid >> 5;
    uint32_t sb = smem_u32(sm);

    const float* kbase = kvb + (size_t)b * HW * CC + h * HD2;
    const float* vbase = kbase + C2;
    const int T0 = split * 7;

    for (int idx = tid; idx < 1176; idx += 256) {
        int q = idx / 24, d = idx % 24;
        sm[OM + q * 28 + d] = m[(size_t)bh * 1176 + idx];
    }
    if (tid < 49) { sm[OMX + tid] = -1e30f; sm[OSM + tid] = 0.f; }

    const int pvc = tid & 3, pvg = tid >> 2;
    const int pq0 = (pvg / 8) * 7, pd0 = (pvg % 8) * 3;
    const bool pv_act = (tid < 224);
    float acc[7][3];
    #pragma unroll
    for (int i = 0; i < 7; i++)
        #pragma unroll
        for (int j = 0; j < 3; j++) acc[i][j] = 0.f;

    const int sqb = tid / 28, skb = tid % 28;
    const int sq0 = sqb * 7;
    const bool sc_act = (tid < 196);

    // prefetch tile 0 of this split
    {
        int kt0 = T0 * KT;
        for (int idx = tid; idx < 1344; idx += 256) {
            int mat = idx / 672, r = (idx % 672) / 6, p = idx % 6;
            const float* src = (mat ? vbase : kbase) + (size_t)(kt0 + r) * CC + p * 4;
            uint32_t dst = sb + ((mat ? OV0 : OK0) + r * 28 + p * 4) * 4;
            cp_async16(dst, src);
        }
        cp_commit();
    }

    for (int t = 0; t < 7; t++) {
        int buf = t & 1;
        if (t + 1 < 7) {
            int kt1 = (T0 + t + 1) * KT;
            int nb = buf ^ 1;
            for (int idx = tid; idx < 1344; idx += 256) {
                int mat = idx / 672, r = (idx % 672) / 6, p = idx % 6;
                const float* src = (mat ? vbase : kbase) + (size_t)(kt1 + r) * CC + p * 4;
                uint32_t dst = sb + ((mat ? (nb ? OV1 : OV0) : (nb ? OK1 : OK0)) + r * 28 + p * 4) * 4;
                cp_async16(dst, src);
            }
            cp_commit();
            cp_wait<1>();
        } else {
            cp_wait<0>();
        }
        __syncthreads();

        if (sc_act) {
            const float4* k4 = (const float4*)(sm + (buf ? OK1 : OK0));
            const float4* m4 = (const float4*)(sm + OM);
            float sc[7][4];
            #pragma unroll
            for (int i = 0; i < 7; i++)
                #pragma unroll
                for (int j = 0; j < 4; j++) sc[i][j] = 0.f;
            #pragma unroll
            for (int d4 = 0; d4 < 6; d4++) {
                float4 kv4[4], mm4[7];
                #pragma unroll
                for (int j = 0; j < 4; j++) kv4[j] = k4[(skb + 28 * j) * 7 + d4];
                #pragma unroll
                for (int i = 0; i < 7; i++) mm4[i] = m4[(sq0 + i) * 7 + d4];
                #pragma unroll
                for (int i = 0; i < 7; i++)
                    #pragma unroll
                    for (int j = 0; j < 4; j++)
                        sc[i][j] += mm4[i].x * kv4[j].x + mm4[i].y * kv4[j].y
                                  + mm4[i].z * kv4[j].z + mm4[i].w * kv4[j].w;
            }
            #pragma unroll
            for (int i = 0; i < 7; i++)
                #pragma unroll
                for (int j = 0; j < 4; j++)
                    sm[OS + (sq0 + i) * 112 + skb + 28 * j] = sc[i][j];
        }
        __syncthreads();

        for (int q = wid; q < 49; q += 8) {
            float* row = sm + OS + q * 112;
            float v0 = row[lane], v1 = row[lane + 32], v2 = row[lane + 64];
            float v3 = (lane < 16) ? row[lane + 96] : -1e30f;
            float tmax = fmaxf(fmaxf(v0, v1), fmaxf(v2, v3));
            #pragma unroll
            for (int off = 16; off; off >>= 1)
                tmax = fmaxf(tmax, __shfl_xor_sync(0xffffffffu, tmax, off));
            float mold = sm[OMX + q];
            float mnew = fmaxf(mold, tmax);
            float e0 = expf(v0 - mnew), e1 = expf(v1 - mnew), e2 = expf(v2 - mnew);
            float e3 = (lane < 16) ? expf(v3 - mnew) : 0.f;
            row[lane] = e0; row[lane + 32] = e1; row[lane + 64] = e2;
            if (lane < 16) row[lane + 96] = e3;
            float tsum = e0 + e1 + e2 + e3;
            #pragma unroll
            for (int off = 16; off; off >>= 1)
                tsum += __shfl_xor_sync(0xffffffffu, tsum, off);
            if (lane == 0) {
                float scale = expf(mold - mnew);
                sm[OSC + q] = scale;
                sm[OSM + q] = sm[OSM + q] * scale + tsum;
                sm[OMX + q] = mnew;
            }
        }
        __syncthreads();

        if (pv_act) {
            #pragma unroll
            for (int i = 0; i < 7; i++) {
                float scl = sm[OSC + pq0 + i];
                #pragma unroll
                for (int j = 0; j < 3; j++) acc[i][j] *= scl;
            }
            const float* vb = sm + (buf ? OV1 : OV0);
            for (int lk = 0; lk < 28; lk++) {
                int kk = pvc * 28 + lk;
                float vv0 = vb[kk * 28 + pd0];
                float vv1 = vb[kk * 28 + pd0 + 1];
                float vv2 = vb[kk * 28 + pd0 + 2];
                #pragma unroll
                for (int i = 0; i < 7; i++) {
                    float pp = sm[OS + (pq0 + i) * 112 + kk];
                    acc[i][0] += pp * vv0;
                    acc[i][1] += pp * vv1;
                    acc[i][2] += pp * vv2;
                }
            }
        }
        __syncthreads();
    }

    // merge 4 chunk partials, write UNNORMALIZED partial + stats
    if (pv_act) {
        #pragma unroll
        for (int i = 0; i < 7; i++)
            #pragma unroll
            for (int j = 0; j < 3; j++)
                sm[OS + ((pq0 + i) * 24 + pd0 + j) * 4 + pvc] = acc[i][j];
    }
    __syncthreads();
    size_t base = (size_t)(bh * NSPLIT + split);
    for (int idx = tid; idx < 1176; idx += 256) {
        float r = sm[OS + idx * 4] + sm[OS + idx * 4 + 1]
                + sm[OS + idx * 4 + 2] + sm[OS + idx * 4 + 3];
        op[base * 1176 + idx] = r;
    }
    if (tid < 49) {
        mxg[base * 49 + tid] = sm[OMX + tid];
        smg[base * 49 + tid] = sm[OSM + tid];
    }
}

// ---------------- attention split merge (log-sum-exp combine) ----------------
__global__ void attn_merge_kernel(const float* __restrict__ op, const float* __restrict__ mxg,
                                  const float* __restrict__ smg, float* __restrict__ o)
{
    __shared__ float wgt[NSPLIT][49];
    __shared__ float den[49];
    int bh = blockIdx.x, tid = threadIdx.x;   // 256 threads
    if (tid < 49) {
        float mx[NSPLIT];
        #pragma unroll
        for (int s = 0; s < NSPLIT; s++) mx[s] = mxg[(size_t)(bh * NSPLIT + s) * 49 + tid];
        float ms = fmaxf(fmaxf(mx[0], mx[1]), fmaxf(mx[2], mx[3]));
        float d = 0.f;
        #pragma unroll
        for (int s = 0; s < NSPLIT; s++) {
            float ww = expf(mx[s] - ms);
            wgt[s][tid] = ww;
            d += smg[(size_t)(bh * NSPLIT + s) * 49 + tid] * ww;
        }
        den[tid] = d;
    }
    __syncthreads();
    for (int idx = tid; idx < 1176; idx += 256) {
        int q = idx / 24;
        float r = 0.f;
        #pragma unroll
        for (int s = 0; s < NSPLIT; s++)
            r += op[(size_t)(bh * NSPLIT + s) * 1176 + idx] * wgt[s][q];
        o[(size_t)bh * 1176 + idx] = r / den[q];
    }
}

// ---------------- concat [q*a | bilinear(o) | cut*xe2], fused upsample ----------------
__global__ void cat_kernel(const __half* __restrict__ q, const __half* __restrict__ a,
                           const float* __restrict__ o, const __half* __restrict__ cut,
                           const __half* __restrict__ xe2, __half* __restrict__ cat)
{
    size_t row = blockIdx.x;
    int t = threadIdx.x;                 // 192 threads, 4 halves each
    __half v[4];
    if (t < 96) {
        int c = t * 4;
        #pragma unroll
        for (int j = 0; j < 4; j++)
            v[j] = __float2half(__half2float(q[row * 384 + c + j]) *
                                __half2float(a[row * 384 + c + j]));
    } else if (t < 144) {
        int c = (t - 96) * 4;
        int b = (int)(row / HW); int rem = (int)(row % HW);
        int y = rem / WW, x = rem % WW;
        int h = c / HD2, d = c % HD2;
        float fy = (y + 0.5f) * 0.125f - 0.5f;
        float fx = (x + 0.5f) * 0.125f - 0.5f;
        int y0 = (int)floorf(fy); float ty = fy - (float)y0;
        int x0 = (int)floorf(fx); float tx = fx - (float)x0;
        int y0c = max(y0, 0), y1c = min(y0 + 1, 6);
        int x0c = max(x0, 0), x1c = min(x0 + 1, 6);
        const float* ob = o + ((size_t)(b * NHD + h) * 49) * HD2 + d;
        float4 v00 = *(const float4*)(ob + (y0c * 7 + x0c) * HD2);
        float4 v01 = *(const float4*)(ob + (y0c * 7 + x1c) * HD2);
        float4 v10 = *(const float4*)(ob + (y1c * 7 + x0c) * HD2);
        float4 v11 = *(const float4*)(ob + (y1c * 7 + x1c) * HD2);
        float w00 = (1.f - ty) * (1.f - tx), w01 = (1.f - ty) * tx;
        float w10 = ty * (1.f - tx), w11 = ty * tx;
        v[0] = __float2half(w00 * v00.x + w01 * v01.x + w10 * v10.x + w11 * v11.x);
        v[1] = __float2half(w00 * v00.y + w01 * v01.y + w10 * v10.y + w11 * v11.y);
        v[2] = __float2half(w00 * v00.z + w01 * v01.z + w10 * v10.z + w11 * v11.z);
        v[3] = __float2half(w00 * v00.w + w01 * v01.w + w10 * v10.w + w11 * v11.w);
    } else {
        int c = (t - 144) * 4;
        #pragma unroll
        for (int j = 0; j < 4; j++)
            v[j] = __float2half(__half2float(cut[row * 192 + c + j]) *
                                __half2float(xe2[row * 192 + c + j]));
    }
    *(uint2*)(cat + row * 768 + t * 4) = *(uint2*)v;
}

// ---------------- launch ----------------
extern "C" void kernel_launch(void* const* d_in, const int* in_sizes, int n_in,
                              void* d_out, int out_size)
{
    const float* x       = (const float*)d_in[0];
    const float* x_e     = (const float*)d_in[1];
    const float* norm_w  = (const float*)d_in[2];
    const float* norm_b  = (const float*)d_in[3];
    const float* norme_w = (const float*)d_in[4];
    const float* norme_b = (const float*)d_in[5];
    const float* q_w     = (const float*)d_in[6];
    const float* q_b     = (const float*)d_in[7];
    const float* qcut_w  = (const float*)d_in[8];
    const float* qcut_b  = (const float*)d_in[9];
    const float* a_w     = (const float*)d_in[10];
    const float* a_b     = (const float*)d_in[11];
    const float* l_w     = (const float*)d_in[12];
    const float* l_b     = (const float*)d_in[13];
    const float* conv_w  = (const float*)d_in[14];
    const float* conv_b  = (const float*)d_in[15];
    const float* econv_w = (const float*)d_in[16];
    const float* econv_b = (const float*)d_in[17];
    const float* efore_w = (const float*)d_in[18];
    const float* efore_b = (const float*)d_in[19];
    const float* eback_w = (const float*)d_in[20];
    const float* eback_b = (const float*)d_in[21];
    const float* kv_w    = (const float*)d_in[22];
    const float* kv_b    = (const float*)d_in[23];
    const float* scl_w   = (const float*)d_in[24];
    const float* scl_b   = (const float*)d_in[25];
    const float* proj_w  = (const float*)d_in[26];
    const float* proj_b  = (const float*)d_in[27];
    const float* proje_w = (const float*)d_in[28];
    const float* proje_b = (const float*)d_in[29];
    float* out = (float*)d_out;
    float* out_x  = out;
    float* out_xe = out + (size_t)MM * CC;

    __half *xn,*xen,*qb,*cutb,*lx,*clx,*ab,*ef,*efc,*xe2,*catb;
    __half *tq,*tl,*ta,*tkv,*tqcut,*tefore,*teback,*tproj,*tproje;
    float *kvb,*mb,*ob,*opb,*mxb,*smb;
    cudaGetSymbolAddress((void**)&xn,   g_xn);
    cudaGetSymbolAddress((void**)&xen,  g_xen);
    cudaGetSymbolAddress((void**)&qb,   g_q);
    cudaGetSymbolAddress((void**)&cutb, g_cut);
    cudaGetSymbolAddress((void**)&lx,   g_lx);
    cudaGetSymbolAddress((void**)&clx,  g_clx);
    cudaGetSymbolAddress((void**)&ab,   g_a);
    cudaGetSymbolAddress((void**)&kvb,  g_kv);
    cudaGetSymbolAddress((void**)&ef,   g_ef);
    cudaGetSymbolAddress((void**)&efc,  g_efc);
    cudaGetSymbolAddress((void**)&xe2,  g_xe2);
    cudaGetSymbolAddress((void**)&mb,   g_m);
    cudaGetSymbolAddress((void**)&ob,   g_o);
    cudaGetSymbolAddress((void**)&opb,  g_op);
    cudaGetSymbolAddress((void**)&mxb,  g_mx);
    cudaGetSymbolAddress((void**)&smb,  g_sm2);
    cudaGetSymbolAddress((void**)&catb, g_cat);
    cudaGetSymbolAddress((void**)&tq,     g_tq);
    cudaGetSymbolAddress((void**)&tl,     g_tl);
    cudaGetSymbolAddress((void**)&ta,     g_ta);
    cudaGetSymbolAddress((void**)&tkv,    g_tkv);
    cudaGetSymbolAddress((void**)&tqcut,  g_tqcut);
    cudaGetSymbolAddress((void**)&tefore, g_tefore);
    cudaGetSymbolAddress((void**)&teback, g_teback);
    cudaGetSymbolAddress((void**)&tproj,  g_tproj);
    cudaGetSymbolAddress((void**)&tproje, g_tproje);

    cudaFuncSetAttribute(h16_gemm_kernel, cudaFuncAttributeMaxDynamicSharedMemorySize, GEMM_SMEM);
    cudaFuncSetAttribute(attn_kernel, cudaFuncAttributeMaxDynamicSharedMemorySize, ATTN_SMEM);

    // 0) all weight transposes in one launch
    transpose_all_kernel<<<4992, 256>>>(q_w, l_w, a_w, kv_w, qcut_w, efore_w, eback_w,
                                        proj_w, proje_w,
                                        tq, tl, ta, tkv, tqcut, tefore, teback, tproj, tproje);

    // 1) LayerNorms (warp per row, half out)
    ln_kernel<<<MM / 8, 256>>>(x,   norm_w,  norm_b,  xn,  CC);
    ln_kernel<<<MM / 8, 256>>>(x_e, norme_w, norme_b, xen, C2);

    // 2) pooled shortcut queries -> m (scaled, fp32)
    pool_scl_kernel<<<BB * 49, 192>>>(xn, xen, scl_w, scl_b, mb);

    // 3) q / cut / lx(gelu) GEMMs (fp16 tensor cores)
    dim3 gN384(3, MM / 128), gN192(2, MM / 128);
    h16_gemm_kernel<<<gN384, 256, GEMM_SMEM>>>(xn, tq,    q_b,    nullptr, qb,   384, 384, 0);
    h16_gemm_kernel<<<gN192, 256, GEMM_SMEM>>>(xn, tqcut, qcut_b, nullptr, cutb, 192, 384, 0);
    h16_gemm_kernel<<<gN384, 256, GEMM_SMEM>>>(xn, tl,    l_b,    nullptr, lx,   384, 384, 1);

    // 4) depthwise conv on lx, then a / kv GEMMs (kv -> fp32 for attention)
    dwconv7_kernel<<<dim3(4, 4, BB * (CC / 16)), 224>>>(lx, conv_w, conv_b, clx, CC);
    h16_gemm_kernel<<<gN384, 256, GEMM_SMEM>>>(clx, ta,  a_b,  nullptr, ab, 384, 384, 0);
    h16_gemm_kernel<<<gN384, 256, GEMM_SMEM>>>(lx,  tkv, kv_b, kvb, nullptr, 384, 384, 0);

    // 5) flash attention (split-K x4) + merge
    attn_kernel<<<BB * NHD * NSPLIT, 256, ATTN_SMEM>>>(kvb, mb, opb, mxb, smb);
    attn_merge_kernel<<<BB * NHD, 256>>>(opb, mxb, smb, ob);

    // 6) x_e depthwise branch
    h16_gemm_kernel<<<gN192, 256, GEMM_SMEM>>>(xen, tefore, efore_b, nullptr, ef, 192, 192, 0);
    dwconv7_kernel<<<dim3(4, 4, BB * (C2 / 16)), 224>>>(ef, econv_w, econv_b, efc, C2);
    h16_gemm_kernel<<<gN192, 256, GEMM_SMEM>>>(efc, teback, eback_b, nullptr, xe2, 192, 192, 0);

    // 7) concat (fused bilinear upsample) + final projections (fp32 out)
    cat_kernel<<<MM, 192>>>(qb, ab, ob, cutb, xe2, catb);
    h16_gemm_kernel<<<gN384, 256, GEMM_SMEM>>>(catb, tproj,  proj_b,  out_x,  nullptr, 384, 768, 0);
    h16_gemm_kernel<<<gN192, 256, GEMM_SMEM>>>(catb, tproje, proje_b, out_xe, nullptr, 192, 768, 0);
}